// round 3
// baseline (speedup 1.0000x reference)
#include <cuda_runtime.h>
#include <cuda_bf16.h>
#include <mma.h>
#include <math.h>
#include <stdint.h>

using namespace nvcuda;
using bf16 = __nv_bfloat16;

// ---------------- problem dims ----------------
constexpr int Bb = 512, Tt = 128, Dd = 128, Hh = 512, MEMN = 64;
constexpr int N1 = 3072;            // 6 gates
constexpr int K1P = 672;            // [h 512 | x 128 | dt 1 | pad 31]
constexpr int N2 = 2560;            // 5 gates from s
constexpr int K2 = 512;

// ---------------- persistent kernel config ----------------
constexpr int NCTA = 128, NTHR = 256;
constexpr int W1_COLS = 48,  W1_LD = 680;
constexpr int W2_COLS = 80,  W2_LD = 520;
constexpr int SA_LD   = 40;                       // staged A row stride (elts)
constexpr int AST_ELTS = 256 * SA_LD;             // per buffer
constexpr size_t SM_AST = (size_t)2 * AST_ELTS * sizeof(bf16);   // 40960
constexpr size_t SM_W1  = (size_t)W1_COLS * W1_LD * sizeof(bf16); // 65280
constexpr size_t SM_W2  = (size_t)W2_COLS * W2_LD * sizeof(bf16); // 83200
constexpr size_t SM_TOTAL = SM_AST + SM_W1 + SM_W2;               // 189440

// ---------------- device scratch ----------------
__device__ bf16  g_AB[Bb * K1P];            // A matrix for phase1: [h | x_t | dt | pad]
__device__ bf16  g_sB[Bb * Hh];             // s_t (bf16)
__device__ float g_G [Bb * N2];             // pre_h[1..5]+pre_x[1..5]+biases
__device__ float g_c [Bb * Hh];
__device__ float g_h [Bb * Hh];
__device__ bf16  g_histB[MEMN * Bb * Hh];   // last 64 h, [m][b][h]
__device__ float g_bias1[N1];
__device__ unsigned g_cnt;
// tail
__device__ float g_qbuf[Bb * 2 * Hh];
__device__ float g_xlast[Bb * Dd];
__device__ float g_qW  [Bb * Hh];
__device__ bf16  g_WahB[Hh * Hh];           // Wah transposed, n-major [n][k]
__device__ float g_hsW [MEMN * Bb * Hh];
__device__ float g_scores[Bb * MEMN];
__device__ float g_e   [Bb * Hh];
__device__ float g_hfin[Bb * Hh];

// ---------------- small helpers ----------------
__device__ __forceinline__ float sigmoidf_(float x) { return 1.f / (1.f + expf(-x)); }

__device__ __forceinline__ void cp16(bf16* dst_smem, const bf16* src) {
    uint32_t d = (uint32_t)__cvta_generic_to_shared(dst_smem);
    asm volatile("cp.async.cg.shared.global [%0], [%1], 16;" :: "r"(d), "l"(src));
}
__device__ __forceinline__ void cp_commit() { asm volatile("cp.async.commit_group;"); }
template <int N>
__device__ __forceinline__ void cp_wait() { asm volatile("cp.async.wait_group %0;" :: "n"(N)); }

__device__ __forceinline__ uint32_t ld2bf(const bf16* p) {
    return *reinterpret_cast<const uint32_t*>(p);
}

__device__ __forceinline__ void mma16816(float* c, uint32_t a0, uint32_t a1, uint32_t a2,
                                         uint32_t a3, uint32_t b0, uint32_t b1) {
    asm volatile(
        "mma.sync.aligned.m16n8k16.row.col.f32.bf16.bf16.f32 "
        "{%0,%1,%2,%3}, {%4,%5,%6,%7}, {%8,%9}, {%0,%1,%2,%3};"
        : "+f"(c[0]), "+f"(c[1]), "+f"(c[2]), "+f"(c[3])
        : "r"(a0), "r"(a1), "r"(a2), "r"(a3), "r"(b0), "r"(b1));
}

// monotonic grid barrier (g_cnt reset by init kernel each launch)
__device__ __forceinline__ void gridbar(unsigned target) {
    __syncthreads();
    if (threadIdx.x == 0) {
        __threadfence();
        atomicAdd(&g_cnt, 1u);
        unsigned v;
        do {
            asm volatile("ld.acquire.gpu.u32 %0, [%1];" : "=r"(v) : "l"(&g_cnt) : "memory");
        } while (v < target);
    }
    __syncthreads();
}

// ---------------- init ----------------
__global__ void k_init2(const float* __restrict__ X, const float* __restrict__ bh_lin,
                        const float* __restrict__ bx_lin, const float* __restrict__ bg,
                        const float* __restrict__ bst) {
    int idx = blockIdx.x * 256 + threadIdx.x;
    if (idx == 0) g_cnt = 0;
    if (idx < N1) {
        float v = bh_lin[idx] + bx_lin[idx] + bg[idx];
        if (idx < 512) v += bst[idx];
        g_bias1[idx] = v;
    }
    if (idx < Bb * Hh) g_c[idx] = 0.f;
    if (idx < Bb * K1P) {
        int b = idx / K1P, cc = idx - b * K1P;
        float v = 0.f;
        if (cc >= 512 && cc < 641) v = X[((size_t)b * Tt + 0) * (Dd + 1) + (cc - 512)];
        g_AB[idx] = __float2bfloat16(v);
    }
}

// ---------------- persistent recurrent kernel ----------------
__global__ void __launch_bounds__(NTHR, 1)
k_recur(const float* __restrict__ X,
        const float* __restrict__ Wh, const float* __restrict__ Wx,
        const float* __restrict__ Wst,
        const float* __restrict__ Ws, const float* __restrict__ bs_lin) {
    extern __shared__ bf16 sm[];
    bf16* ast = sm;
    bf16* w1s = sm + 2 * AST_ELTS;
    bf16* w2s = w1s + W1_COLS * W1_LD;

    const int tid = threadIdx.x, cta = blockIdx.x;
    const int w = tid >> 5, lane = tid & 31;
    const int lq = lane >> 2, lr = lane & 3;

    // phase1 mapping: 64 col-tiles (48) x 2 m-tiles (256)
    const int ci = cta >> 1, mi1 = cta & 1;
    const int col0 = ci * W1_COLS, m01 = mi1 * 256;
    // phase2 mapping: 32 hh-tiles (16) x 4 m-tiles (128)
    const int hi = cta >> 2, mi2 = cta & 3;
    const int hh0 = hi * 16, m02 = mi2 * 128;

    // ---- load weight slices (once per launch) ----
    for (int idx = tid; idx < W1_COLS * K1P; idx += NTHR) {
        int n = idx / K1P, k = idx - n * K1P;
        int col = col0 + n, g = col >> 9, hh = col & 511;
        float v = 0.f;
        if (k < 512)      v = Wh[((size_t)(g * 512 + k)) * 512 + hh];
        else if (k < 640) v = Wx[((size_t)(g * 128 + (k - 512))) * 512 + hh];
        else if (k == 640) v = (g == 0) ? Wst[hh] : 0.f;
        w1s[n * W1_LD + k] = __float2bfloat16(v);
    }
    // W2 slice: storage row nl = (p*5+q)*8 + c  <->  global col = q*512 + hh0 + p*8 + c
    for (int idx = tid; idx < W2_COLS * K2; idx += NTHR) {
        int nl = idx / K2, k = idx - nl * K2;
        int blk = nl >> 3, c = nl & 7, p = blk / 5, q = blk - p * 5;
        int hh = hh0 + p * 8 + c;
        w2s[nl * W2_LD + k] = __float2bfloat16(Ws[((size_t)(q * 512 + k)) * 512 + hh]);
    }
    __syncthreads();

    const int wm1 = w >> 1, wn1 = w & 1;   // phase1 warp: 64 rows x 24 cols
    const int wm2 = w >> 1, wn2 = w & 1;   // phase2 warp: 32 rows x 40 cols (5 gates x 8 hh)

    unsigned bar = 0;

    for (int t = 0; t < Tt; t++) {
        // ============ phase 1: pre = [h|x|dt] @ W1 -> s, G ============
        {
            float acc[4][3][4];
#pragma unroll
            for (int i = 0; i < 4; i++)
#pragma unroll
                for (int j = 0; j < 3; j++)
#pragma unroll
                    for (int r = 0; r < 4; r++) acc[i][j][r] = 0.f;

            // stage chunk 0 (256 rows x 32 k)
            {
                const bf16* src = g_AB + (size_t)(m01 + tid) * K1P;
                bf16* dst = ast + tid * SA_LD;
                cp16(dst, src); cp16(dst + 8, src + 8);
                cp16(dst + 16, src + 16); cp16(dst + 24, src + 24);
                cp_commit();
            }
            for (int ch = 0; ch < 21; ch++) {
                if (ch < 20) {
                    const bf16* src = g_AB + (size_t)(m01 + tid) * K1P + (ch + 1) * 32;
                    bf16* dst = ast + ((ch + 1) & 1) * AST_ELTS + tid * SA_LD;
                    cp16(dst, src); cp16(dst + 8, src + 8);
                    cp16(dst + 16, src + 16); cp16(dst + 24, src + 24);
                    cp_commit();
                    cp_wait<1>();
                } else {
                    cp_wait<0>();
                }
                __syncthreads();
                const bf16* ab = ast + (ch & 1) * AST_ELTS;
                const int kc = ch * 32;
#pragma unroll
                for (int half = 0; half < 2; half++) {
                    const int kk = half * 16;
                    uint32_t areg[4][4];
#pragma unroll
                    for (int im = 0; im < 4; im++) {
                        const bf16* ap = ab + (wm1 * 64 + im * 16 + lq) * SA_LD + kk + lr * 2;
                        areg[im][0] = ld2bf(ap);
                        areg[im][1] = ld2bf(ap + 8 * SA_LD);
                        areg[im][2] = ld2bf(ap + 8);
                        areg[im][3] = ld2bf(ap + 8 * SA_LD + 8);
                    }
#pragma unroll
                    for (int jn = 0; jn < 3; jn++) {
                        const bf16* bp = w1s + (wn1 * 24 + jn * 8 + lq) * W1_LD + kc + kk + lr * 2;
                        uint32_t b0 = ld2bf(bp), b1 = ld2bf(bp + 8);
#pragma unroll
                        for (int im = 0; im < 4; im++)
                            mma16816(acc[im][jn], areg[im][0], areg[im][1],
                                     areg[im][2], areg[im][3], b0, b1);
                    }
                }
                __syncthreads();
            }
            // epilogue: s (gate 0, tanh, bf16) and G (gates 1..5, fp32)
#pragma unroll
            for (int im = 0; im < 4; im++) {
                int rbase = m01 + wm1 * 64 + im * 16 + lq;
#pragma unroll
                for (int jn = 0; jn < 3; jn++) {
                    int cbase = col0 + wn1 * 24 + jn * 8 + lr * 2;
#pragma unroll
                    for (int hf = 0; hf < 2; hf++) {
                        int row = rbase + hf * 8;
#pragma unroll
                        for (int e = 0; e < 2; e++) {
                            int col = cbase + e;
                            float val = acc[im][jn][hf * 2 + e] + g_bias1[col];
                            if (col < 512)
                                g_sB[row * 512 + col] = __float2bfloat16(tanhf(val));
                            else
                                g_G[(size_t)row * N2 + (col - 512)] = val;
                        }
                    }
                }
            }
        }
        bar += NCTA; gridbar(bar);

        // ============ phase 2: pre_s = s @ W2, fused gate+state update ============
        {
            float acc[2][5][4];
#pragma unroll
            for (int i = 0; i < 2; i++)
#pragma unroll
                for (int j = 0; j < 5; j++)
#pragma unroll
                    for (int r = 0; r < 4; r++) acc[i][j][r] = 0.f;

            // stage chunk 0 (128 rows x 32 k): thread -> (row=tid/2, part=tid&1)
            {
                int row = tid >> 1, part = tid & 1;
                const bf16* src = g_sB + (size_t)(m02 + row) * 512 + part * 16;
                bf16* dst = ast + row * SA_LD + part * 16;
                cp16(dst, src); cp16(dst + 8, src + 8);
                cp_commit();
            }
            for (int ch = 0; ch < 16; ch++) {
                if (ch < 15) {
                    int row = tid >> 1, part = tid & 1;
                    const bf16* src = g_sB + (size_t)(m02 + row) * 512 + (ch + 1) * 32 + part * 16;
                    bf16* dst = ast + ((ch + 1) & 1) * AST_ELTS + row * SA_LD + part * 16;
                    cp16(dst, src); cp16(dst + 8, src + 8);
                    cp_commit();
                    cp_wait<1>();
                } else {
                    cp_wait<0>();
                }
                __syncthreads();
                const bf16* ab = ast + (ch & 1) * AST_ELTS;
                const int kc = ch * 32;
#pragma unroll
                for (int half = 0; half < 2; half++) {
                    const int kk = half * 16;
                    uint32_t areg[2][4];
#pragma unroll
                    for (int im = 0; im < 2; im++) {
                        const bf16* ap = ab + (wm2 * 32 + im * 16 + lq) * SA_LD + kk + lr * 2;
                        areg[im][0] = ld2bf(ap);
                        areg[im][1] = ld2bf(ap + 8 * SA_LD);
                        areg[im][2] = ld2bf(ap + 8);
                        areg[im][3] = ld2bf(ap + 8 * SA_LD + 8);
                    }
#pragma unroll
                    for (int q = 0; q < 5; q++) {
                        const bf16* bp = w2s + ((wn2 * 5 + q) * 8 + lq) * W2_LD + kc + kk + lr * 2;
                        uint32_t b0 = ld2bf(bp), b1 = ld2bf(bp + 8);
#pragma unroll
                        for (int im = 0; im < 2; im++)
                            mma16816(acc[im][q], areg[im][0], areg[im][1],
                                     areg[im][2], areg[im][3], b0, b1);
                    }
                }
                __syncthreads();
            }
            // epilogue: all 5 gates of (b,hh) are thread-local -> fused LSTM update
#pragma unroll
            for (int im = 0; im < 2; im++) {
#pragma unroll
                for (int hf = 0; hf < 2; hf++) {
                    int b = m02 + wm2 * 32 + im * 16 + lq + hf * 8;
#pragma unroll
                    for (int e = 0; e < 2; e++) {
                        int hh = hh0 + wn2 * 8 + lr * 2 + e;
                        float v[5];
#pragma unroll
                        for (int q = 0; q < 5; q++)
                            v[q] = acc[im][q][hf * 2 + e]
                                 + g_G[(size_t)b * N2 + q * 512 + hh]
                                 + bs_lin[q * 512 + hh];
                        float f  = sigmoidf_(v[0]);
                        float i_ = sigmoidf_(v[1]);
                        float Tg = sigmoidf_(v[2]);
                        float z  = tanhf(v[3]);
                        float o  = sigmoidf_(v[4]);
                        float s  = __bfloat162float(g_sB[b * 512 + hh]);
                        float cn = f * g_c[b * 512 + hh] + i_ * z + Tg * s;
                        g_c[b * 512 + hh] = cn;
                        float hv = o * tanhf(cn);
                        g_h[b * 512 + hh] = hv;
                        g_AB[(size_t)b * K1P + hh] = __float2bfloat16(hv);
                        if (t >= Tt - MEMN)
                            g_histB[(size_t)(t - (Tt - MEMN)) * (Bb * Hh) + b * 512 + hh] =
                                __float2bfloat16(hv);
                    }
                }
            }
            // stage x_{t+1} (+dt) into A matrix (done by hh-tile-0 CTAs)
            if (hi == 0 && t < Tt - 1) {
                for (int idx = tid; idx < 128 * 129; idx += NTHR) {
                    int r = idx / 129, d = idx - r * 129;
                    int b = m02 + r;
                    g_AB[(size_t)b * K1P + 512 + d] =
                        __float2bfloat16(X[((size_t)b * Tt + (t + 1)) * (Dd + 1) + d]);
                }
            }
        }
        bar += NCTA; gridbar(bar);
    }
}

// ---------------- tail: hsW = hist(bf16) @ WahB(bf16), bf16 mma, double-buffered ----------------
__global__ void __launch_bounds__(256) k_hsw() {
    __shared__ bf16 as[2][128 * SA_LD];
    __shared__ bf16 bs[2][128 * SA_LD];
    const int tid = threadIdx.x, w = tid >> 5, lane = tid & 31;
    const int lq = lane >> 2, lr = lane & 3;
    const int row0 = blockIdx.y * 128, col0 = blockIdx.x * 128;
    const int wm = w >> 1, wn = w & 1;   // warp: 32 rows x 64 cols

    float acc[2][8][4];
#pragma unroll
    for (int i = 0; i < 2; i++)
#pragma unroll
        for (int j = 0; j < 8; j++)
#pragma unroll
            for (int r = 0; r < 4; r++) acc[i][j][r] = 0.f;

    {
        int r = tid >> 1, part = tid & 1;
        const bf16* sa = g_histB + (size_t)(row0 + r) * 512 + part * 16;
        const bf16* sb = g_WahB + (size_t)(col0 + r) * 512 + part * 16;
        bf16* da = &as[0][r * SA_LD + part * 16];
        bf16* db = &bs[0][r * SA_LD + part * 16];
        cp16(da, sa); cp16(da + 8, sa + 8);
        cp16(db, sb); cp16(db + 8, sb + 8);
        cp_commit();
    }
    for (int ch = 0; ch < 16; ch++) {
        if (ch < 15) {
            int r = tid >> 1, part = tid & 1;
            const bf16* sa = g_histB + (size_t)(row0 + r) * 512 + (ch + 1) * 32 + part * 16;
            const bf16* sb = g_WahB + (size_t)(col0 + r) * 512 + (ch + 1) * 32 + part * 16;
            int buf = (ch + 1) & 1;
            bf16* da = &as[buf][r * SA_LD + part * 16];
            bf16* db = &bs[buf][r * SA_LD + part * 16];
            cp16(da, sa); cp16(da + 8, sa + 8);
            cp16(db, sb); cp16(db + 8, sb + 8);
            cp_commit();
            cp_wait<1>();
        } else {
            cp_wait<0>();
        }
        __syncthreads();
        const bf16* ab = as[ch & 1];
        const bf16* bb = bs[ch & 1];
#pragma unroll
        for (int half = 0; half < 2; half++) {
            const int kk = half * 16;
            uint32_t areg[2][4];
#pragma unroll
            for (int im = 0; im < 2; im++) {
                const bf16* ap = ab + (wm * 32 + im * 16 + lq) * SA_LD + kk + lr * 2;
                areg[im][0] = ld2bf(ap);
                areg[im][1] = ld2bf(ap + 8 * SA_LD);
                areg[im][2] = ld2bf(ap + 8);
                areg[im][3] = ld2bf(ap + 8 * SA_LD + 8);
            }
#pragma unroll
            for (int jn = 0; jn < 8; jn++) {
                const bf16* bp = bb + (wn * 64 + jn * 8 + lq) * SA_LD + kk + lr * 2;
                uint32_t b0 = ld2bf(bp), b1 = ld2bf(bp + 8);
#pragma unroll
                for (int im = 0; im < 2; im++)
                    mma16816(acc[im][jn], areg[im][0], areg[im][1],
                             areg[im][2], areg[im][3], b0, b1);
            }
        }
        __syncthreads();
    }
#pragma unroll
    for (int im = 0; im < 2; im++)
#pragma unroll
        for (int jn = 0; jn < 8; jn++)
#pragma unroll
            for (int hf = 0; hf < 2; hf++)
#pragma unroll
                for (int e = 0; e < 2; e++) {
                    int row = row0 + wm * 32 + im * 16 + lq + hf * 8;
                    int col = col0 + wn * 64 + jn * 8 + lr * 2 + e;
                    g_hsW[(size_t)row * 512 + col] = acc[im][jn][hf * 2 + e];
                }
}

__global__ void k_prepWah(const float* __restrict__ Wah) {
    int idx = blockIdx.x * 256 + threadIdx.x;
    if (idx < Hh * Hh) {
        int k = idx >> 9, n = idx & 511;
        g_WahB[n * 512 + k] = __float2bfloat16(Wah[k * 512 + n]);
    }
}

// ---------------- tf32 wmma plain GEMM (small tail GEMMs) ----------------
constexpr int LDA = 68, LDB = 132;
constexpr int SMEM_BYTES = (128 * LDA + 64 * LDB) * 4;

using FragA = wmma::fragment<wmma::matrix_a, 16, 16, 8, wmma::precision::tf32, wmma::row_major>;
using FragB = wmma::fragment<wmma::matrix_b, 16, 16, 8, wmma::precision::tf32, wmma::row_major>;
using FragC = wmma::fragment<wmma::accumulator, 16, 16, 8, float>;

__device__ __forceinline__ void mma_chunk(FragC (&acc)[2][4], const float* As, const float* Bs,
                                          int wm, int wn) {
#pragma unroll
    for (int kk = 0; kk < 64; kk += 8) {
        FragA a0, a1;
        wmma::load_matrix_sync(a0, As + (wm * 32) * LDA + kk, LDA);
        wmma::load_matrix_sync(a1, As + (wm * 32 + 16) * LDA + kk, LDA);
#pragma unroll
        for (int j = 0; j < 4; j++) {
            FragB bf;
            wmma::load_matrix_sync(bf, Bs + kk * LDB + wn * 64 + j * 16, LDB);
            wmma::mma_sync(acc[0][j], a0, bf, acc[0][j]);
            wmma::mma_sync(acc[1][j], a1, bf, acc[1][j]);
        }
    }
}

__global__ void k_gemm_plain(const float* __restrict__ A, int lda,
                             const float* __restrict__ Bp, int ldb,
                             float* __restrict__ C, int ldc, int K, int beta) {
    extern __shared__ float smf[];
    float* As = smf;
    float* Bs = smf + 128 * LDA;
    float* Cs = smf;
    const int tid = threadIdx.x, wid = tid >> 5, wm = wid >> 1, wn = wid & 1;
    const int row0 = blockIdx.y * 128, col0 = blockIdx.x * 128;

    FragC acc[2][4];
#pragma unroll
    for (int i = 0; i < 2; i++)
#pragma unroll
        for (int j = 0; j < 4; j++) wmma::fill_fragment(acc[i][j], 0.f);

    for (int kc = 0; kc < K; kc += 64) {
        for (int e = tid; e < 8192; e += 256) {
            int r = e >> 6, k = e & 63, kg = kc + k;
            float v = (kg < K) ? A[(size_t)(row0 + r) * lda + kg] : 0.f;
            As[r * LDA + k] = wmma::__float_to_tf32(v);
        }
        for (int e = tid; e < 8192; e += 256) {
            int k = e >> 7, cc = e & 127, kg = kc + k;
            float v = (kg < K) ? Bp[(size_t)kg * ldb + col0 + cc] : 0.f;
            Bs[k * LDB + cc] = wmma::__float_to_tf32(v);
        }
        __syncthreads();
        mma_chunk(acc, As, Bs, wm, wn);
        __syncthreads();
    }
#pragma unroll
    for (int i = 0; i < 2; i++)
#pragma unroll
        for (int j = 0; j < 4; j++)
            wmma::store_matrix_sync(Cs + (wm * 32 + i * 16) * 128 + wn * 64 + j * 16,
                                    acc[i][j], 128, wmma::mem_row_major);
    __syncthreads();
    for (int e = tid; e < 16384; e += 256) {
        int r = e >> 7, cc = e & 127;
        size_t idx = (size_t)(row0 + r) * ldc + col0 + cc;
        C[idx] = Cs[e] + (beta ? C[idx] : 0.f);
    }
}

// ---------------- tail elementwise kernels ----------------
__global__ void k_prep(const float* __restrict__ X) {
    int idx = blockIdx.x * 256 + threadIdx.x;
    if (idx < Bb * 2 * Hh) {
        int b = idx >> 10, k = idx & 1023;
        g_qbuf[idx] = (k < Hh) ? g_h[b * Hh + k] : g_c[b * Hh + (k - Hh)];
    }
    if (idx < Bb * Dd) {
        int b = idx >> 7, d = idx & 127;
        g_xlast[idx] = X[((size_t)b * Tt + (Tt - 1)) * (Dd + 1) + d];
    }
}

__global__ void k_scores(const float* __restrict__ baq, const float* __restrict__ bah,
                         const float* __restrict__ vt) {
    int wid = threadIdx.x >> 5, lane = threadIdx.x & 31;
    int r = blockIdx.x * 8 + wid;   // r = m*512 + b
    int b = r & 511;
    float acc = 0.f;
    for (int hh = lane; hh < Hh; hh += 32) {
        float x = g_hsW[(size_t)r * Hh + hh] + g_qW[b * Hh + hh] + baq[hh] + bah[hh];
        acc += tanhf(x) * vt[hh];
    }
#pragma unroll
    for (int o = 16; o; o >>= 1) acc += __shfl_down_sync(0xffffffffu, acc, o);
    if (lane == 0) g_scores[b * MEMN + (r >> 9)] = acc;
}

__global__ void k_softmax_e() {
    int b = blockIdx.x, tid = threadIdx.x;
    __shared__ float al[MEMN];
    __shared__ float ssum;
    if (tid < MEMN) al[tid] = expf(g_scores[b * MEMN + tid]);
    __syncthreads();
    if (tid == 0) {
        float s = 0.f;
        for (int m = 0; m < MEMN; m++) s += al[m];
        ssum = s;
    }
    __syncthreads();
    float inv = 1.f / ssum;
    for (int hh = tid; hh < Hh; hh += 256) {
        float acc = 0.f;
        for (int m = 0; m < MEMN; m++)
            acc += al[m] * __bfloat162float(g_histB[(size_t)m * (Bb * Hh) + b * Hh + hh]);
        g_e[b * Hh + hh] = acc * inv;
    }
}

__global__ void k_final(const float* __restrict__ b_Wh, const float* __restrict__ b_We,
                        const float* __restrict__ b_Wg, const float* __restrict__ bh_p,
                        const float* __restrict__ Wc, const float* __restrict__ bc,
                        float* __restrict__ out) {
    int b = blockIdx.x, tid = threadIdx.x;
    __shared__ float red[256];
    float acc = 0.f;
    for (int hh = tid; hh < Hh; hh += 256) {
        float hf = tanhf(g_hfin[b * Hh + hh] + b_Wh[hh] + b_We[hh] + b_Wg[hh] + bh_p[hh]);
        acc += hf * Wc[hh];
    }
    red[tid] = acc;
    __syncthreads();
    for (int s = 128; s; s >>= 1) {
        if (tid < s) red[tid] += red[tid + s];
        __syncthreads();
    }
    if (tid == 0) out[b] = 1.f / (1.f + expf(-(red[0] + bc[0])));
}

// ---------------- launch ----------------
extern "C" void kernel_launch(void* const* d_in, const int* in_sizes, int n_in,
                              void* d_out, int out_size) {
    const float* X      = (const float*)d_in[0];
    const float* Wh     = (const float*)d_in[1];
    const float* bh_lin = (const float*)d_in[2];
    const float* Wx     = (const float*)d_in[3];
    const float* bx_lin = (const float*)d_in[4];
    const float* Wst    = (const float*)d_in[5];
    const float* bst    = (const float*)d_in[6];
    const float* Ws     = (const float*)d_in[7];
    const float* bs_lin = (const float*)d_in[8];
    const float* bg     = (const float*)d_in[9];
    const float* Waq    = (const float*)d_in[10];
    const float* baq    = (const float*)d_in[11];
    const float* Wah    = (const float*)d_in[12];
    const float* bah    = (const float*)d_in[13];
    const float* vt     = (const float*)d_in[14];
    const float* W_h    = (const float*)d_in[15];
    const float* b_Wh   = (const float*)d_in[16];
    const float* We     = (const float*)d_in[17];
    const float* b_We   = (const float*)d_in[18];
    const float* Wg     = (const float*)d_in[19];
    const float* b_Wg   = (const float*)d_in[20];
    const float* bh_p   = (const float*)d_in[21];
    const float* Wc     = (const float*)d_in[22];
    const float* bc     = (const float*)d_in[23];
    float* out = (float*)d_out;

    cudaFuncSetAttribute(k_recur, cudaFuncAttributeMaxDynamicSharedMemorySize, (int)SM_TOTAL);
    cudaFuncSetAttribute(k_gemm_plain, cudaFuncAttributeMaxDynamicSharedMemorySize, SMEM_BYTES);

    float *p_qbuf, *p_qW, *p_h, *p_e, *p_xlast, *p_hfin;
    cudaGetSymbolAddress((void**)&p_qbuf,  g_qbuf);
    cudaGetSymbolAddress((void**)&p_qW,    g_qW);
    cudaGetSymbolAddress((void**)&p_h,     g_h);
    cudaGetSymbolAddress((void**)&p_e,     g_e);
    cudaGetSymbolAddress((void**)&p_xlast, g_xlast);
    cudaGetSymbolAddress((void**)&p_hfin,  g_hfin);

    k_init2<<<(Bb * K1P + 255) / 256, 256>>>(X, bh_lin, bx_lin, bg, bst);
    k_recur<<<NCTA, NTHR, SM_TOTAL>>>(X, Wh, Wx, Wst, Ws, bs_lin);

    // attention + readout
    k_prepWah<<<(Hh * Hh + 255) / 256, 256>>>(Wah);
    k_prep<<<(Bb * 2 * Hh + 255) / 256, 256>>>(X);
    k_gemm_plain<<<dim3(4, 4), 256, SMEM_BYTES>>>(p_qbuf, 2 * Hh, Waq, Hh, p_qW, Hh, 2 * Hh, 0);
    k_hsw<<<dim3(4, 256), 256>>>();
    k_scores<<<(MEMN * Bb) / 8, 256>>>(baq, bah, vt);
    k_softmax_e<<<Bb, 256>>>();
    k_gemm_plain<<<dim3(4, 4), 256, SMEM_BYTES>>>(p_h,     Hh, W_h, Hh, p_hfin, Hh, Hh, 0);
    k_gemm_plain<<<dim3(4, 4), 256, SMEM_BYTES>>>(p_e,     Hh, We,  Hh, p_hfin, Hh, Hh, 1);
    k_gemm_plain<<<dim3(4, 4), 256, SMEM_BYTES>>>(p_xlast, Dd, Wg,  Hh, p_hfin, Hh, Dd, 1);
    k_final<<<Bb, 256>>>(b_Wh, b_We, b_Wg, bh_p, Wc, bc, out);
}

// round 4
// speedup vs baseline: 1.8710x; 1.8710x over previous
#include <cuda_runtime.h>
#include <cuda_bf16.h>
#include <mma.h>
#include <math.h>
#include <stdint.h>

using namespace nvcuda;
using bf16 = __nv_bfloat16;

constexpr int Bb = 512, Tt = 128, Dd = 128, Hh = 512, MEMN = 64;
constexpr int NCTA = 128, NTHR = 256;
constexpr int LD1 = 648, LD2 = 520, LDA_S = 40;
constexpr int STG_ELTS = 128 * LDA_S;  // 5120 per buffer
// smem: w1s 96x648 | w2s 80x520 | staging 2x5120  (bf16)
constexpr size_t SM_RECUR = (size_t)(96 * LD1 + 80 * LD2 + 2 * STG_ELTS) * 2;  // 228096

// ---------------- device scratch ----------------
__device__ bf16  g_AB[Bb * 640];           // [b][ h(512) | x_t(128) ]
__device__ bf16  g_sB[Bb * Hh];            // s_t
__device__ float g_c[Bb * Hh], g_h[Bb * Hh];
__device__ bf16  g_histB[MEMN * Bb * Hh];  // [m][b][h]
__device__ unsigned g_cnt;
// tail scratch
__device__ float g_qbuf[Bb * 2 * Hh];
__device__ float g_xlast[Bb * Dd];
__device__ float g_qW[Bb * Hh];
__device__ bf16  g_WahB[Hh * Hh];
__device__ float g_hsW[MEMN * Bb * Hh];
__device__ float g_scores[Bb * MEMN];
__device__ float g_e[Bb * Hh];
__device__ float g_hfin[Bb * Hh];

// ---------------- helpers ----------------
__device__ __forceinline__ float sigmoidf_(float x) { return 1.f / (1.f + expf(-x)); }

__device__ __forceinline__ uint32_t packbf(float lo, float hi) {
    uint32_t r;
    asm("cvt.rn.bf16x2.f32 %0, %1, %2;" : "=r"(r) : "f"(hi), "f"(lo));
    return r;
}

__device__ __forceinline__ void cp16(bf16* dst_smem, const bf16* src) {
    uint32_t d = (uint32_t)__cvta_generic_to_shared(dst_smem);
    asm volatile("cp.async.cg.shared.global [%0], [%1], 16;" :: "r"(d), "l"(src));
}
__device__ __forceinline__ void cp_commit() { asm volatile("cp.async.commit_group;"); }
template <int N>
__device__ __forceinline__ void cp_wait() { asm volatile("cp.async.wait_group %0;" :: "n"(N)); }

__device__ __forceinline__ uint32_t ld2bf(const bf16* p) {
    return *reinterpret_cast<const uint32_t*>(p);
}

__device__ __forceinline__ void mma16816(float* c, uint32_t a0, uint32_t a1, uint32_t a2,
                                         uint32_t a3, uint32_t b0, uint32_t b1) {
    asm volatile(
        "mma.sync.aligned.m16n8k16.row.col.f32.bf16.bf16.f32 "
        "{%0,%1,%2,%3}, {%4,%5,%6,%7}, {%8,%9}, {%0,%1,%2,%3};"
        : "+f"(c[0]), "+f"(c[1]), "+f"(c[2]), "+f"(c[3])
        : "r"(a0), "r"(a1), "r"(a2), "r"(a3), "r"(b0), "r"(b1));
}

__device__ __forceinline__ void gridbar(unsigned target) {
    __syncthreads();
    if (threadIdx.x == 0) {
        __threadfence();
        atomicAdd(&g_cnt, 1u);
        unsigned v;
        do {
            asm volatile("ld.acquire.gpu.u32 %0, [%1];" : "=r"(v) : "l"(&g_cnt) : "memory");
        } while (v < target);
    }
    __syncthreads();
}

// ---------------- init ----------------
__global__ void k_init(const float* __restrict__ X) {
    int idx = blockIdx.x * 256 + threadIdx.x;
    if (idx == 0) g_cnt = 0;
    if (idx < Bb * 640) {
        int b = idx / 640, k = idx - b * 640;
        float v = (k >= 512) ? X[((size_t)b * Tt + 0) * (Dd + 1) + (k - 512)] : 0.f;
        g_AB[idx] = __float2bfloat16(v);
    }
}

// ---------------- persistent recurrent kernel ----------------
__global__ void __launch_bounds__(NTHR, 1)
k_recur(const float* __restrict__ X,
        const float* __restrict__ Wh, const float* __restrict__ Wx,
        const float* __restrict__ Wst, const float* __restrict__ Ws,
        const float* __restrict__ bh_lin, const float* __restrict__ bx_lin,
        const float* __restrict__ bg, const float* __restrict__ bst,
        const float* __restrict__ bs_lin) {
    extern __shared__ bf16 sm[];
    bf16* w1s = sm;
    bf16* w2s = sm + 96 * LD1;
    bf16* stg = w2s + 80 * LD2;

    const int tid = threadIdx.x, cta = blockIdx.x;
    const int w = tid >> 5, lane = tid & 31;
    const int lq = lane >> 2, lr = lane & 3;
    const int wm = w >> 1, wn = w & 1;          // 4x2 warps: 32 rows x 48/40 cols
    const int mi = cta & 3, hi = cta >> 2;
    const int m0 = mi * 128, hh0 = hi * 16;

    // ---- weight slices into SMEM (once) ----
    // W1 row n: wn_=n/48, jn=(n%48)/8, c=n%8 -> gate g (jn<5: jn+1, jn==5: 0), hh=hh0+wn_*8+c
    for (int idx = tid; idx < 96 * 640; idx += NTHR) {
        int n = idx / 640, k = idx - n * 640;
        int wn_ = n / 48, rem = n - wn_ * 48, jn = rem >> 3, c = rem & 7;
        int g = (jn < 5) ? jn + 1 : 0;
        int hh = hh0 + wn_ * 8 + c;
        float v = (k < 512) ? Wh[((size_t)(g * 512 + k)) * 512 + hh]
                            : Wx[((size_t)(g * 128 + (k - 512))) * 512 + hh];
        w1s[n * LD1 + k] = __float2bfloat16(v);
    }
    for (int idx = tid; idx < 80 * 512; idx += NTHR) {
        int n = idx >> 9, k = idx & 511;
        int wn_ = n / 40, rem = n - wn_ * 40, jn = rem >> 3, c = rem & 7;
        int hh = hh0 + wn_ * 8 + c;
        w2s[n * LD2 + k] = __float2bfloat16(Ws[((size_t)(jn * 512 + k)) * 512 + hh]);
    }
    __syncthreads();

    // ---- per-thread constants ----
    const int hhp = hh0 + wn * 8 + lr * 2;      // this thread's hidden pair base
    float biasG[5][2], bias0[2], wstv[2];
#pragma unroll
    for (int e = 0; e < 2; e++) {
        int hh = hhp + e;
        bias0[e] = bh_lin[hh] + bx_lin[hh] + bg[hh] + bst[hh];
        wstv[e] = Wst[hh];
#pragma unroll
        for (int q = 0; q < 5; q++) {
            int gc = (q + 1) * 512 + hh;
            biasG[q][e] = bh_lin[gc] + bx_lin[gc] + bg[gc] + bs_lin[q * 512 + hh];
        }
    }

    float c_reg[2][2][2], s_reg[2][2][2];
#pragma unroll
    for (int i = 0; i < 2; i++)
#pragma unroll
        for (int j = 0; j < 2; j++) { c_reg[i][j][0] = 0.f; c_reg[i][j][1] = 0.f; }

    unsigned bar = 0;

    for (int t = 0; t < Tt; t++) {
        float acc[2][6][4];
#pragma unroll
        for (int i = 0; i < 2; i++)
#pragma unroll
            for (int j = 0; j < 6; j++)
#pragma unroll
                for (int r = 0; r < 4; r++) acc[i][j][r] = 0.f;

        // ===== phase 1: [h|x] @ W1 (K=640, 20 chunks) =====
        {
            int r = tid >> 1, ho = (tid & 1) * 16;
            const bf16* src = g_AB + (size_t)(m0 + r) * 640 + ho;
            bf16* dst = stg + r * LDA_S + ho;
            cp16(dst, src); cp16(dst + 8, src + 8);
            cp_commit();
        }
        for (int ch = 0; ch < 20; ch++) {
            if (ch < 19) {
                int r = tid >> 1, ho = (tid & 1) * 16;
                const bf16* src = g_AB + (size_t)(m0 + r) * 640 + (ch + 1) * 32 + ho;
                bf16* dst = stg + ((ch + 1) & 1) * STG_ELTS + r * LDA_S + ho;
                cp16(dst, src); cp16(dst + 8, src + 8);
                cp_commit(); cp_wait<1>();
            } else cp_wait<0>();
            __syncthreads();
            const bf16* ab = stg + (ch & 1) * STG_ELTS;
            const int kc = ch * 32;
#pragma unroll
            for (int half = 0; half < 2; half++) {
                const int kk = half * 16;
                uint32_t ar[2][4];
#pragma unroll
                for (int im = 0; im < 2; im++) {
                    const bf16* ap = ab + (wm * 32 + im * 16 + lq) * LDA_S + kk + lr * 2;
                    ar[im][0] = ld2bf(ap);
                    ar[im][1] = ld2bf(ap + 8 * LDA_S);
                    ar[im][2] = ld2bf(ap + 8);
                    ar[im][3] = ld2bf(ap + 8 * LDA_S + 8);
                }
#pragma unroll
                for (int jn = 0; jn < 6; jn++) {
                    const bf16* bp = w1s + (wn * 48 + jn * 8 + lq) * LD1 + kc + kk + lr * 2;
                    uint32_t b0 = ld2bf(bp), b1 = ld2bf(bp + 8);
                    mma16816(acc[0][jn], ar[0][0], ar[0][1], ar[0][2], ar[0][3], b0, b1);
                    mma16816(acc[1][jn], ar[1][0], ar[1][1], ar[1][2], ar[1][3], b0, b1);
                }
            }
            __syncthreads();
        }
        // mid epilogue: s = tanh(pre0 + dt*Wst + bias); keep in regs, publish bf16
#pragma unroll
        for (int im = 0; im < 2; im++)
#pragma unroll
            for (int hf = 0; hf < 2; hf++) {
                int b = m0 + wm * 32 + im * 16 + lq + hf * 8;
                float dt = X[((size_t)b * Tt + t) * (Dd + 1) + Dd];
                float s0 = tanhf(acc[im][5][hf * 2 + 0] + bias0[0] + dt * wstv[0]);
                float s1 = tanhf(acc[im][5][hf * 2 + 1] + bias0[1] + dt * wstv[1]);
                s_reg[im][hf][0] = s0; s_reg[im][hf][1] = s1;
                *reinterpret_cast<uint32_t*>(&g_sB[(size_t)b * 512 + hhp]) = packbf(s0, s1);
            }
        bar += NCTA; gridbar(bar);

        // ===== phase 2: s @ Ws accumulates onto same acc (K=512, 16 chunks) =====
        {
            int r = tid >> 1, ho = (tid & 1) * 16;
            const bf16* src = g_sB + (size_t)(m0 + r) * 512 + ho;
            bf16* dst = stg + r * LDA_S + ho;
            cp16(dst, src); cp16(dst + 8, src + 8);
            cp_commit();
        }
        for (int ch = 0; ch < 16; ch++) {
            if (ch < 15) {
                int r = tid >> 1, ho = (tid & 1) * 16;
                const bf16* src = g_sB + (size_t)(m0 + r) * 512 + (ch + 1) * 32 + ho;
                bf16* dst = stg + ((ch + 1) & 1) * STG_ELTS + r * LDA_S + ho;
                cp16(dst, src); cp16(dst + 8, src + 8);
                cp_commit(); cp_wait<1>();
            } else cp_wait<0>();
            __syncthreads();
            const bf16* ab = stg + (ch & 1) * STG_ELTS;
            const int kc = ch * 32;
#pragma unroll
            for (int half = 0; half < 2; half++) {
                const int kk = half * 16;
                uint32_t ar[2][4];
#pragma unroll
                for (int im = 0; im < 2; im++) {
                    const bf16* ap = ab + (wm * 32 + im * 16 + lq) * LDA_S + kk + lr * 2;
                    ar[im][0] = ld2bf(ap);
                    ar[im][1] = ld2bf(ap + 8 * LDA_S);
                    ar[im][2] = ld2bf(ap + 8);
                    ar[im][3] = ld2bf(ap + 8 * LDA_S + 8);
                }
#pragma unroll
                for (int jn = 0; jn < 5; jn++) {
                    const bf16* bp = w2s + (wn * 40 + jn * 8 + lq) * LD2 + kc + kk + lr * 2;
                    uint32_t b0 = ld2bf(bp), b1 = ld2bf(bp + 8);
                    mma16816(acc[0][jn], ar[0][0], ar[0][1], ar[0][2], ar[0][3], b0, b1);
                    mma16816(acc[1][jn], ar[1][0], ar[1][1], ar[1][2], ar[1][3], b0, b1);
                }
            }
            __syncthreads();
        }
        // end epilogue: fused LSTM state update, c/h in registers
#pragma unroll
        for (int im = 0; im < 2; im++)
#pragma unroll
            for (int hf = 0; hf < 2; hf++) {
                int b = m0 + wm * 32 + im * 16 + lq + hf * 8;
                float h2[2];
#pragma unroll
                for (int e = 0; e < 2; e++) {
                    float f  = sigmoidf_(acc[im][0][hf * 2 + e] + biasG[0][e]);
                    float i_ = sigmoidf_(acc[im][1][hf * 2 + e] + biasG[1][e]);
                    float Tg = sigmoidf_(acc[im][2][hf * 2 + e] + biasG[2][e]);
                    float z  = tanhf(acc[im][3][hf * 2 + e] + biasG[3][e]);
                    float o  = sigmoidf_(acc[im][4][hf * 2 + e] + biasG[4][e]);
                    float cn = f * c_reg[im][hf][e] + i_ * z + Tg * s_reg[im][hf][e];
                    c_reg[im][hf][e] = cn;
                    h2[e] = o * tanhf(cn);
                }
                uint32_t hp = packbf(h2[0], h2[1]);
                *reinterpret_cast<uint32_t*>(&g_AB[(size_t)b * 640 + hhp]) = hp;
                if (t >= Tt - MEMN)
                    *reinterpret_cast<uint32_t*>(
                        &g_histB[(size_t)(t - (Tt - MEMN)) * (Bb * Hh) + b * 512 + hhp]) = hp;
                if (t == Tt - 1) {
                    g_h[b * 512 + hhp]     = h2[0];
                    g_h[b * 512 + hhp + 1] = h2[1];
                    g_c[b * 512 + hhp]     = c_reg[im][hf][0];
                    g_c[b * 512 + hhp + 1] = c_reg[im][hf][1];
                }
            }
        // stage x_{t+1}: CTA covers d-slice [hi*4, hi*4+4) for its 128 rows
        if (t < Tt - 1) {
            for (int i = tid; i < 512; i += NTHR) {
                int r = i >> 2, j = i & 3;
                int b = m0 + r, d = hi * 4 + j;
                g_AB[(size_t)b * 640 + 512 + d] =
                    __float2bfloat16(X[((size_t)b * Tt + (t + 1)) * (Dd + 1) + d]);
            }
        }
        bar += NCTA; gridbar(bar);
    }
}

// ---------------- tail: hsW = hist @ Wah^T (bf16 mma, double-buffered) ----------------
__global__ void __launch_bounds__(256) k_hsw() {
    __shared__ bf16 as[2][128 * 40];
    __shared__ bf16 bs[2][128 * 40];
    const int tid = threadIdx.x, w = tid >> 5, lane = tid & 31;
    const int lq = lane >> 2, lr = lane & 3;
    const int row0 = blockIdx.y * 128, col0 = blockIdx.x * 128;
    const int wm = w >> 1, wn = w & 1;

    float acc[2][8][4];
#pragma unroll
    for (int i = 0; i < 2; i++)
#pragma unroll
        for (int j = 0; j < 8; j++)
#pragma unroll
            for (int r = 0; r < 4; r++) acc[i][j][r] = 0.f;

    {
        int r = tid >> 1, part = (tid & 1) * 16;
        const bf16* sa = g_histB + (size_t)(row0 + r) * 512 + part;
        const bf16* sb = g_WahB + (size_t)(col0 + r) * 512 + part;
        cp16(&as[0][r * 40 + part], sa); cp16(&as[0][r * 40 + part + 8], sa + 8);
        cp16(&bs[0][r * 40 + part], sb); cp16(&bs[0][r * 40 + part + 8], sb + 8);
        cp_commit();
    }
    for (int ch = 0; ch < 16; ch++) {
        if (ch < 15) {
            int r = tid >> 1, part = (tid & 1) * 16;
            const bf16* sa = g_histB + (size_t)(row0 + r) * 512 + (ch + 1) * 32 + part;
            const bf16* sb = g_WahB + (size_t)(col0 + r) * 512 + (ch + 1) * 32 + part;
            int buf = (ch + 1) & 1;
            cp16(&as[buf][r * 40 + part], sa); cp16(&as[buf][r * 40 + part + 8], sa + 8);
            cp16(&bs[buf][r * 40 + part], sb); cp16(&bs[buf][r * 40 + part + 8], sb + 8);
            cp_commit(); cp_wait<1>();
        } else cp_wait<0>();
        __syncthreads();
        const bf16* ab = as[ch & 1];
        const bf16* bb = bs[ch & 1];
#pragma unroll
        for (int half = 0; half < 2; half++) {
            const int kk = half * 16;
            uint32_t ar[2][4];
#pragma unroll
            for (int im = 0; im < 2; im++) {
                const bf16* ap = ab + (wm * 32 + im * 16 + lq) * 40 + kk + lr * 2;
                ar[im][0] = ld2bf(ap); ar[im][1] = ld2bf(ap + 8 * 40);
                ar[im][2] = ld2bf(ap + 8); ar[im][3] = ld2bf(ap + 8 * 40 + 8);
            }
#pragma unroll
            for (int jn = 0; jn < 8; jn++) {
                const bf16* bp = bb + (wn * 64 + jn * 8 + lq) * 40 + kk + lr * 2;
                uint32_t b0 = ld2bf(bp), b1 = ld2bf(bp + 8);
                mma16816(acc[0][jn], ar[0][0], ar[0][1], ar[0][2], ar[0][3], b0, b1);
                mma16816(acc[1][jn], ar[1][0], ar[1][1], ar[1][2], ar[1][3], b0, b1);
            }
        }
        __syncthreads();
    }
#pragma unroll
    for (int im = 0; im < 2; im++)
#pragma unroll
        for (int jn = 0; jn < 8; jn++)
#pragma unroll
            for (int hf = 0; hf < 2; hf++)
#pragma unroll
                for (int e = 0; e < 2; e++) {
                    int row = row0 + wm * 32 + im * 16 + lq + hf * 8;
                    int col = col0 + wn * 64 + jn * 8 + lr * 2 + e;
                    g_hsW[(size_t)row * 512 + col] = acc[im][jn][hf * 2 + e];
                }
}

__global__ void k_prepWah(const float* __restrict__ Wah) {
    int idx = blockIdx.x * 256 + threadIdx.x;
    if (idx < Hh * Hh) {
        int k = idx >> 9, n = idx & 511;
        g_WahB[n * 512 + k] = __float2bfloat16(Wah[k * 512 + n]);
    }
}

// ---------------- tf32 wmma plain GEMM (small tail GEMMs) ----------------
constexpr int PLDA = 68, PLDB = 132;
constexpr int SMEM_BYTES = (128 * PLDA + 64 * PLDB) * 4;

using FragA = wmma::fragment<wmma::matrix_a, 16, 16, 8, wmma::precision::tf32, wmma::row_major>;
using FragB = wmma::fragment<wmma::matrix_b, 16, 16, 8, wmma::precision::tf32, wmma::row_major>;
using FragC = wmma::fragment<wmma::accumulator, 16, 16, 8, float>;

__global__ void k_gemm_plain(const float* __restrict__ A, int lda,
                             const float* __restrict__ Bp, int ldb,
                             float* __restrict__ C, int ldc, int K, int beta) {
    extern __shared__ float smf[];
    float* As = smf;
    float* Bs = smf + 128 * PLDA;
    float* Cs = smf;
    const int tid = threadIdx.x, wid = tid >> 5, wm = wid >> 1, wn = wid & 1;
    const int row0 = blockIdx.y * 128, col0 = blockIdx.x * 128;

    FragC acc[2][4];
#pragma unroll
    for (int i = 0; i < 2; i++)
#pragma unroll
        for (int j = 0; j < 4; j++) wmma::fill_fragment(acc[i][j], 0.f);

    for (int kc = 0; kc < K; kc += 64) {
        for (int e = tid; e < 8192; e += 256) {
            int r = e >> 6, k = e & 63, kg = kc + k;
            float v = (kg < K) ? A[(size_t)(row0 + r) * lda + kg] : 0.f;
            As[r * PLDA + k] = wmma::__float_to_tf32(v);
        }
        for (int e = tid; e < 8192; e += 256) {
            int k = e >> 7, cc = e & 127, kg = kc + k;
            float v = (kg < K) ? Bp[(size_t)kg * ldb + col0 + cc] : 0.f;
            Bs[k * PLDB + cc] = wmma::__float_to_tf32(v);
        }
        __syncthreads();
#pragma unroll
        for (int kk = 0; kk < 64; kk += 8) {
            FragA a0, a1;
            wmma::load_matrix_sync(a0, As + (wm * 32) * PLDA + kk, PLDA);
            wmma::load_matrix_sync(a1, As + (wm * 32 + 16) * PLDA + kk, PLDA);
#pragma unroll
            for (int j = 0; j < 4; j++) {
                FragB bf;
                wmma::load_matrix_sync(bf, Bs + kk * PLDB + wn * 64 + j * 16, PLDB);
                wmma::mma_sync(acc[0][j], a0, bf, acc[0][j]);
                wmma::mma_sync(acc[1][j], a1, bf, acc[1][j]);
            }
        }
        __syncthreads();
    }
#pragma unroll
    for (int i = 0; i < 2; i++)
#pragma unroll
        for (int j = 0; j < 4; j++)
            wmma::store_matrix_sync(Cs + (wm * 32 + i * 16) * 128 + wn * 64 + j * 16,
                                    acc[i][j], 128, wmma::mem_row_major);
    __syncthreads();
    for (int e = tid; e < 16384; e += 256) {
        int r = e >> 7, cc = e & 127;
        size_t idx = (size_t)(row0 + r) * ldc + col0 + cc;
        C[idx] = Cs[e] + (beta ? C[idx] : 0.f);
    }
}

// ---------------- tail elementwise ----------------
__global__ void k_prep(const float* __restrict__ X) {
    int idx = blockIdx.x * 256 + threadIdx.x;
    if (idx < Bb * 2 * Hh) {
        int b = idx >> 10, k = idx & 1023;
        g_qbuf[idx] = (k < Hh) ? g_h[b * Hh + k] : g_c[b * Hh + (k - Hh)];
    }
    if (idx < Bb * Dd) {
        int b = idx >> 7, d = idx & 127;
        g_xlast[idx] = X[((size_t)b * Tt + (Tt - 1)) * (Dd + 1) + d];
    }
}

__global__ void k_scores(const float* __restrict__ baq, const float* __restrict__ bah,
                         const float* __restrict__ vt) {
    int wid = threadIdx.x >> 5, lane = threadIdx.x & 31;
    int r = blockIdx.x * 8 + wid;
    int b = r & 511;
    float acc = 0.f;
    for (int hh = lane; hh < Hh; hh += 32) {
        float x = g_hsW[(size_t)r * Hh + hh] + g_qW[b * Hh + hh] + baq[hh] + bah[hh];
        acc += tanhf(x) * vt[hh];
    }
#pragma unroll
    for (int o = 16; o; o >>= 1) acc += __shfl_down_sync(0xffffffffu, acc, o);
    if (lane == 0) g_scores[b * MEMN + (r >> 9)] = acc;
}

__global__ void k_softmax_e() {
    int b = blockIdx.x, tid = threadIdx.x;
    __shared__ float al[MEMN];
    __shared__ float ssum;
    if (tid < MEMN) al[tid] = expf(g_scores[b * MEMN + tid]);
    __syncthreads();
    if (tid == 0) {
        float s = 0.f;
        for (int m = 0; m < MEMN; m++) s += al[m];
        ssum = s;
    }
    __syncthreads();
    float inv = 1.f / ssum;
    for (int hh = tid; hh < Hh; hh += 256) {
        float acc = 0.f;
        for (int m = 0; m < MEMN; m++)
            acc += al[m] * __bfloat162float(g_histB[(size_t)m * (Bb * Hh) + b * Hh + hh]);
        g_e[b * Hh + hh] = acc * inv;
    }
}

__global__ void k_final(const float* __restrict__ b_Wh, const float* __restrict__ b_We,
                        const float* __restrict__ b_Wg, const float* __restrict__ bh_p,
                        const float* __restrict__ Wc, const float* __restrict__ bc,
                        float* __restrict__ out) {
    int b = blockIdx.x, tid = threadIdx.x;
    __shared__ float red[256];
    float acc = 0.f;
    for (int hh = tid; hh < Hh; hh += 256) {
        float hf = tanhf(g_hfin[b * Hh + hh] + b_Wh[hh] + b_We[hh] + b_Wg[hh] + bh_p[hh]);
        acc += hf * Wc[hh];
    }
    red[tid] = acc;
    __syncthreads();
    for (int s = 128; s; s >>= 1) {
        if (tid < s) red[tid] += red[tid + s];
        __syncthreads();
    }
    if (tid == 0) out[b] = 1.f / (1.f + expf(-(red[0] + bc[0])));
}

// ---------------- launch ----------------
extern "C" void kernel_launch(void* const* d_in, const int* in_sizes, int n_in,
                              void* d_out, int out_size) {
    const float* X      = (const float*)d_in[0];
    const float* Wh     = (const float*)d_in[1];
    const float* bh_lin = (const float*)d_in[2];
    const float* Wx     = (const float*)d_in[3];
    const float* bx_lin = (const float*)d_in[4];
    const float* Wst    = (const float*)d_in[5];
    const float* bst    = (const float*)d_in[6];
    const float* Ws     = (const float*)d_in[7];
    const float* bs_lin = (const float*)d_in[8];
    const float* bg     = (const float*)d_in[9];
    const float* Waq    = (const float*)d_in[10];
    const float* baq    = (const float*)d_in[11];
    const float* Wah    = (const float*)d_in[12];
    const float* bah    = (const float*)d_in[13];
    const float* vt     = (const float*)d_in[14];
    const float* W_h    = (const float*)d_in[15];
    const float* b_Wh   = (const float*)d_in[16];
    const float* We     = (const float*)d_in[17];
    const float* b_We   = (const float*)d_in[18];
    const float* Wg     = (const float*)d_in[19];
    const float* b_Wg   = (const float*)d_in[20];
    const float* bh_p   = (const float*)d_in[21];
    const float* Wc     = (const float*)d_in[22];
    const float* bc     = (const float*)d_in[23];
    float* out = (float*)d_out;

    cudaFuncSetAttribute(k_recur, cudaFuncAttributeMaxDynamicSharedMemorySize, (int)SM_RECUR);
    cudaFuncSetAttribute(k_gemm_plain, cudaFuncAttributeMaxDynamicSharedMemorySize, SMEM_BYTES);

    float *p_qbuf, *p_qW, *p_h, *p_e, *p_xlast, *p_hfin;
    cudaGetSymbolAddress((void**)&p_qbuf,  g_qbuf);
    cudaGetSymbolAddress((void**)&p_qW,    g_qW);
    cudaGetSymbolAddress((void**)&p_h,     g_h);
    cudaGetSymbolAddress((void**)&p_e,     g_e);
    cudaGetSymbolAddress((void**)&p_xlast, g_xlast);
    cudaGetSymbolAddress((void**)&p_hfin,  g_hfin);

    k_init<<<(Bb * 640 + 255) / 256, 256>>>(X);
    k_recur<<<NCTA, NTHR, SM_RECUR>>>(X, Wh, Wx, Wst, Ws,
                                      bh_lin, bx_lin, bg, bst, bs_lin);

    k_prepWah<<<(Hh * Hh + 255) / 256, 256>>>(Wah);
    k_prep<<<(Bb * 2 * Hh + 255) / 256, 256>>>(X);
    k_gemm_plain<<<dim3(4, 4), 256, SMEM_BYTES>>>(p_qbuf, 2 * Hh, Waq, Hh, p_qW, Hh, 2 * Hh, 0);
    k_hsw<<<dim3(4, 256), 256>>>();
    k_scores<<<(MEMN * Bb) / 8, 256>>>(baq, bah, vt);
    k_softmax_e<<<Bb, 256>>>();
    k_gemm_plain<<<dim3(4, 4), 256, SMEM_BYTES>>>(p_h,     Hh, W_h, Hh, p_hfin, Hh, Hh, 0);
    k_gemm_plain<<<dim3(4, 4), 256, SMEM_BYTES>>>(p_e,     Hh, We,  Hh, p_hfin, Hh, Hh, 1);
    k_gemm_plain<<<dim3(4, 4), 256, SMEM_BYTES>>>(p_xlast, Dd, Wg,  Hh, p_hfin, Hh, Dd, 1);
    k_final<<<Bb, 256>>>(b_Wh, b_We, b_Wg, bh_p, Wc, bc, out);
}

// round 6
// speedup vs baseline: 2.4624x; 1.3161x over previous
#include <cuda_runtime.h>
#include <cuda_bf16.h>
#include <mma.h>
#include <math.h>
#include <stdint.h>

using namespace nvcuda;
using bf16 = __nv_bfloat16;

constexpr int Bb = 512, Tt = 128, Dd = 128, Hh = 512, MEMN = 64;
constexpr int NCTA = 128, NTHR = 256;
constexpr int LD1 = 648, LD2 = 520;          // weight smem row strides (elems, 16B-aligned)
constexpr int SO_W1 = 0;
constexpr int SO_W2 = 96 * LD1 * 2;          // 124416
constexpr int SO_STG = SO_W2 + 80 * LD2 * 2; // 207616
constexpr int STG_BYTES = 128 * 64;          // 8192 per stage (128 rows x 64B, swizzled)
constexpr int SM_RECUR = SO_STG + 3 * STG_BYTES;  // 232192

// ---------------- device scratch ----------------
__device__ bf16  g_AB[Bb * 640];           // [b][ h(512) | x_t(128) ]
__device__ bf16  g_sB[Bb * Hh];            // s_t
__device__ float g_c[Bb * Hh], g_h[Bb * Hh];
__device__ bf16  g_histB[MEMN * Bb * Hh];  // [m][b][h]
__device__ unsigned g_cnt;
// tail scratch
__device__ float g_qbuf[Bb * 2 * Hh];
__device__ float g_xlast[Bb * Dd];
__device__ float g_qW[Bb * Hh];
__device__ bf16  g_WahB[Hh * Hh];
__device__ float g_hsW[MEMN * Bb * Hh];
__device__ float g_scores[Bb * MEMN];
__device__ float g_e[Bb * Hh];
__device__ float g_hfin[Bb * Hh];

// ---------------- helpers ----------------
__device__ __forceinline__ float sigmoidf_(float x) { return 1.f / (1.f + expf(-x)); }

__device__ __forceinline__ uint32_t packbf(float lo, float hi) {
    uint32_t r;
    asm("cvt.rn.bf16x2.f32 %0, %1, %2;" : "=r"(r) : "f"(hi), "f"(lo));
    return r;
}
__device__ __forceinline__ uint32_t smem_u32(const void* p) {
    uint32_t a;
    asm("{ .reg .u64 t; cvta.to.shared.u64 t, %1; cvt.u32.u64 %0, t; }" : "=r"(a) : "l"(p));
    return a;
}
__device__ __forceinline__ void cp16b(uint32_t dst, const bf16* src) {
    asm volatile("cp.async.cg.shared.global [%0], [%1], 16;" :: "r"(dst), "l"(src));
}
__device__ __forceinline__ void cp16(bf16* dst_smem, const bf16* src) {
    uint32_t d = (uint32_t)__cvta_generic_to_shared(dst_smem);
    asm volatile("cp.async.cg.shared.global [%0], [%1], 16;" :: "r"(d), "l"(src));
}
__device__ __forceinline__ void cp_commit() { asm volatile("cp.async.commit_group;"); }
template <int N>
__device__ __forceinline__ void cp_wait() { asm volatile("cp.async.wait_group %0;" :: "n"(N)); }

__device__ __forceinline__ void ldsm4(uint32_t* r, uint32_t a) {
    asm volatile("ldmatrix.sync.aligned.m8n8.x4.shared.b16 {%0,%1,%2,%3}, [%4];"
                 : "=r"(r[0]), "=r"(r[1]), "=r"(r[2]), "=r"(r[3]) : "r"(a));
}
__device__ __forceinline__ void ldsm2(uint32_t* r, uint32_t a) {
    asm volatile("ldmatrix.sync.aligned.m8n8.x2.shared.b16 {%0,%1}, [%2];"
                 : "=r"(r[0]), "=r"(r[1]) : "r"(a));
}
__device__ __forceinline__ uint32_t ld2bf(const bf16* p) {
    return *reinterpret_cast<const uint32_t*>(p);
}
__device__ __forceinline__ void mma16816(float* c, uint32_t a0, uint32_t a1, uint32_t a2,
                                         uint32_t a3, uint32_t b0, uint32_t b1) {
    asm volatile(
        "mma.sync.aligned.m16n8k16.row.col.f32.bf16.bf16.f32 "
        "{%0,%1,%2,%3}, {%4,%5,%6,%7}, {%8,%9}, {%0,%1,%2,%3};"
        : "+f"(c[0]), "+f"(c[1]), "+f"(c[2]), "+f"(c[3])
        : "r"(a0), "r"(a1), "r"(a2), "r"(a3), "r"(b0), "r"(b1));
}
__device__ __forceinline__ void gridbar(unsigned target) {
    __syncthreads();
    if (threadIdx.x == 0) {
        __threadfence();
        atomicAdd(&g_cnt, 1u);
        unsigned v;
        do {
            asm volatile("ld.acquire.gpu.u32 %0, [%1];" : "=r"(v) : "l"(&g_cnt) : "memory");
        } while (v < target);
    }
    __syncthreads();
}

// ---------------- init ----------------
__global__ void k_init(const float* __restrict__ X) {
    int idx = blockIdx.x * 256 + threadIdx.x;
    if (idx == 0) g_cnt = 0;
    if (idx < Bb * 640) {
        int b = idx / 640, k = idx - b * 640;
        float v = (k >= 512) ? X[((size_t)b * Tt + 0) * (Dd + 1) + (k - 512)] : 0.f;
        g_AB[idx] = __float2bfloat16(v);
    }
}

// ---------------- persistent recurrent kernel ----------------
__global__ void __launch_bounds__(NTHR, 1)
k_recur(const float* __restrict__ X,
        const float* __restrict__ Wh, const float* __restrict__ Wx,
        const float* __restrict__ Wst, const float* __restrict__ Ws,
        const float* __restrict__ bh_lin, const float* __restrict__ bx_lin,
        const float* __restrict__ bg, const float* __restrict__ bst,
        const float* __restrict__ bs_lin) {
    extern __shared__ __align__(16) bf16 sm[];
    const uint32_t sbase = smem_u32(sm);
    const uint32_t w1u = sbase + SO_W1, w2u = sbase + SO_W2, stgu = sbase + SO_STG;
    bf16* w1s = sm;
    bf16* w2s = sm + 96 * LD1;

    const int tid = threadIdx.x, cta = blockIdx.x;
    const int w = tid >> 5, lane = tid & 31;
    const int lq = lane >> 2, lr = lane & 3;
    const int wm = w >> 1, wn = w & 1;          // 4x2 warps: 32 rows x 48/40 cols
    const int mi = cta & 3, hi = cta >> 2;
    const int m0 = mi * 128, hh0 = hi * 16;

    // ---- weight slices into SMEM (once) ----
    for (int idx = tid; idx < 96 * 640; idx += NTHR) {
        int n = idx / 640, k = idx - n * 640;
        int wn_ = n / 48, rem = n - wn_ * 48, jn = rem >> 3, c = rem & 7;
        int g = (jn < 5) ? jn + 1 : 0;
        int hh = hh0 + wn_ * 8 + c;
        float v = (k < 512) ? Wh[((size_t)(g * 512 + k)) * 512 + hh]
                            : Wx[((size_t)(g * 128 + (k - 512))) * 512 + hh];
        w1s[n * LD1 + k] = __float2bfloat16(v);
    }
    for (int idx = tid; idx < 80 * 512; idx += NTHR) {
        int n = idx >> 9, k = idx & 511;
        int wn_ = n / 40, rem = n - wn_ * 40, jn = rem >> 3, c = rem & 7;
        int hh = hh0 + wn_ * 8 + c;
        w2s[n * LD2 + k] = __float2bfloat16(Ws[((size_t)(jn * 512 + k)) * 512 + hh]);
    }
    __syncthreads();

    // ---- per-thread constants ----
    const int hhp = hh0 + wn * 8 + lr * 2;
    float biasG[5][2], bias0[2], wstv[2];
#pragma unroll
    for (int e = 0; e < 2; e++) {
        int hh = hhp + e;
        bias0[e] = bh_lin[hh] + bx_lin[hh] + bg[hh] + bst[hh];
        wstv[e] = Wst[hh];
#pragma unroll
        for (int q = 0; q < 5; q++) {
            int gc = (q + 1) * 512 + hh;
            biasG[q][e] = bh_lin[gc] + bx_lin[gc] + bg[gc] + bs_lin[q * 512 + hh];
        }
    }

    // ---- precomputed ldmatrix address components ----
    // A (staged, swizzled): R = wm*32 + im*16 + (lane&15); seg s = half*2 + (lane>>4)
    const int hi4 = (lane >> 4) & 1;
    uint32_t rowA[2], swzA[2];
#pragma unroll
    for (int im = 0; im < 2; im++) {
        int R = wm * 32 + im * 16 + (lane & 15);
        rowA[im] = (uint32_t)R * 64u;
        swzA[im] = (uint32_t)((R >> 1) & 3);
    }
    // B phase1: pair p covers jn = 2p, 2p+1
    uint32_t boff1[3];
#pragma unroll
    for (int p = 0; p < 3; p++) {
        int n = wn * 48 + p * 16 + (lane & 7) + ((lane & 16) >> 1);
        boff1[p] = (uint32_t)n * (LD1 * 2) + ((lane & 8) << 1);
    }
    // B phase2: pairs p=0,1 (jn 0-3), x2 for jn=4
    uint32_t boff2[2], boff2x;
#pragma unroll
    for (int p = 0; p < 2; p++) {
        int n = wn * 40 + p * 16 + (lane & 7) + ((lane & 16) >> 1);
        boff2[p] = (uint32_t)n * (LD2 * 2) + ((lane & 8) << 1);
    }
    {
        int n = wn * 40 + 32 + (lane & 7);
        boff2x = (uint32_t)n * (LD2 * 2) + ((lane & 8) << 1);
    }
    // staging writer: row r = tid>>1, segs s0, s0+1
    const int str = tid >> 1, ss0 = (tid & 1) * 2;
    const uint32_t swr = (uint32_t)((str >> 1) & 3);
    const uint32_t wdst0 = (uint32_t)str * 64u + (((uint32_t)ss0 ^ swr) & 3u) * 16u;
    const uint32_t wdst1 = (uint32_t)str * 64u + (((uint32_t)(ss0 + 1) ^ swr) & 3u) * 16u;

    float c_reg[2][2][2], s_reg[2][2][2];
#pragma unroll
    for (int i = 0; i < 2; i++)
#pragma unroll
        for (int j = 0; j < 2; j++) { c_reg[i][j][0] = 0.f; c_reg[i][j][1] = 0.f; }

    unsigned bar = 0;

    for (int t = 0; t < Tt; t++) {
        float acc[2][6][4];
#pragma unroll
        for (int i = 0; i < 2; i++)
#pragma unroll
            for (int j = 0; j < 6; j++)
#pragma unroll
                for (int r = 0; r < 4; r++) acc[i][j][r] = 0.f;

        // ===== phase 1: [h|x] @ W1, K=640, 20 chunks, 3-stage pipeline =====
        {
            const bf16* arow = g_AB + (size_t)(m0 + str) * 640 + ss0 * 8;
            // prologue: stage chunks 0,1
            cp16b(stgu + 0 * STG_BYTES + wdst0, arow);
            cp16b(stgu + 0 * STG_BYTES + wdst1, arow + 8);
            cp_commit();
            cp16b(stgu + 1 * STG_BYTES + wdst0, arow + 32);
            cp16b(stgu + 1 * STG_BYTES + wdst1, arow + 40);
            cp_commit();
            int st = 0;
            for (int ch = 0; ch < 20; ch++) {
                if (ch < 19) cp_wait<1>(); else cp_wait<0>();
                __syncthreads();
                if (ch + 2 < 20) {
                    int s2 = st + 2; if (s2 >= 3) s2 -= 3;
                    const bf16* src = arow + (ch + 2) * 32;
                    cp16b(stgu + s2 * STG_BYTES + wdst0, src);
                    cp16b(stgu + s2 * STG_BYTES + wdst1, src + 8);
                    cp_commit();
                }
                const uint32_t abuf = stgu + st * STG_BYTES;
                const uint32_t kb = (uint32_t)ch * 64u;
#pragma unroll
                for (int half = 0; half < 2; half++) {
                    uint32_t A0[4], A1[4], Bv[12];
                    uint32_t sseg = (uint32_t)(half * 2 + hi4);
                    ldsm4(A0, abuf + rowA[0] + ((sseg ^ swzA[0]) & 3u) * 16u);
                    ldsm4(A1, abuf + rowA[1] + ((sseg ^ swzA[1]) & 3u) * 16u);
                    uint32_t kw = kb + (uint32_t)half * 32u;
                    ldsm4(Bv + 0, w1u + boff1[0] + kw);
                    ldsm4(Bv + 4, w1u + boff1[1] + kw);
                    ldsm4(Bv + 8, w1u + boff1[2] + kw);
#pragma unroll
                    for (int jn = 0; jn < 6; jn++) {
                        mma16816(acc[0][jn], A0[0], A0[1], A0[2], A0[3], Bv[2 * jn], Bv[2 * jn + 1]);
                        mma16816(acc[1][jn], A1[0], A1[1], A1[2], A1[3], Bv[2 * jn], Bv[2 * jn + 1]);
                    }
                }
                if (++st == 3) st = 0;
            }
        }
        // mid epilogue: s = tanh(pre0 + dt*Wst + bias); keep in regs, publish bf16
#pragma unroll
        for (int im = 0; im < 2; im++)
#pragma unroll
            for (int hf = 0; hf < 2; hf++) {
                int b = m0 + wm * 32 + im * 16 + lq + hf * 8;
                float dt = X[((size_t)b * Tt + t) * (Dd + 1) + Dd];
                float s0 = tanhf(acc[im][5][hf * 2 + 0] + bias0[0] + dt * wstv[0]);
                float s1 = tanhf(acc[im][5][hf * 2 + 1] + bias0[1] + dt * wstv[1]);
                s_reg[im][hf][0] = s0; s_reg[im][hf][1] = s1;
                *reinterpret_cast<uint32_t*>(&g_sB[(size_t)b * 512 + hhp]) = packbf(s0, s1);
            }
        bar += NCTA; gridbar(bar);

        // ===== phase 2: s @ Ws accumulates onto same acc, K=512, 16 chunks =====
        {
            const bf16* srow = g_sB + (size_t)(m0 + str) * 512 + ss0 * 8;
            cp16b(stgu + 0 * STG_BYTES + wdst0, srow);
            cp16b(stgu + 0 * STG_BYTES + wdst1, srow + 8);
            cp_commit();
            cp16b(stgu + 1 * STG_BYTES + wdst0, srow + 32);
            cp16b(stgu + 1 * STG_BYTES + wdst1, srow + 40);
            cp_commit();
            int st = 0;
            for (int ch = 0; ch < 16; ch++) {
                if (ch < 15) cp_wait<1>(); else cp_wait<0>();
                __syncthreads();
                if (ch + 2 < 16) {
                    int s2 = st + 2; if (s2 >= 3) s2 -= 3;
                    const bf16* src = srow + (ch + 2) * 32;
                    cp16b(stgu + s2 * STG_BYTES + wdst0, src);
                    cp16b(stgu + s2 * STG_BYTES + wdst1, src + 8);
                    cp_commit();
                }
                const uint32_t abuf = stgu + st * STG_BYTES;
                const uint32_t kb = (uint32_t)ch * 64u;
#pragma unroll
                for (int half = 0; half < 2; half++) {
                    uint32_t A0[4], A1[4], Bv[10];
                    uint32_t sseg = (uint32_t)(half * 2 + hi4);
                    ldsm4(A0, abuf + rowA[0] + ((sseg ^ swzA[0]) & 3u) * 16u);
                    ldsm4(A1, abuf + rowA[1] + ((sseg ^ swzA[1]) & 3u) * 16u);
                    uint32_t kw = kb + (uint32_t)half * 32u;
                    ldsm4(Bv + 0, w2u + boff2[0] + kw);
                    ldsm4(Bv + 4, w2u + boff2[1] + kw);
                    ldsm2(Bv + 8, w2u + boff2x + kw);
#pragma unroll
                    for (int jn = 0; jn < 5; jn++) {
                        mma16816(acc[0][jn], A0[0], A0[1], A0[2], A0[3], Bv[2 * jn], Bv[2 * jn + 1]);
                        mma16816(acc[1][jn], A1[0], A1[1], A1[2], A1[3], Bv[2 * jn], Bv[2 * jn + 1]);
                    }
                }
                if (++st == 3) st = 0;
            }
        }
        // end epilogue: fused LSTM state update (c in registers)
#pragma unroll
        for (int im = 0; im < 2; im++)
#pragma unroll
            for (int hf = 0; hf < 2; hf++) {
                int b = m0 + wm * 32 + im * 16 + lq + hf * 8;
                float h2[2];
#pragma unroll
                for (int e = 0; e < 2; e++) {
                    float f  = sigmoidf_(acc[im][0][hf * 2 + e] + biasG[0][e]);
                    float i_ = sigmoidf_(acc[im][1][hf * 2 + e] + biasG[1][e]);
                    float Tg = sigmoidf_(acc[im][2][hf * 2 + e] + biasG[2][e]);
                    float z  = tanhf(acc[im][3][hf * 2 + e] + biasG[3][e]);
                    float o  = sigmoidf_(acc[im][4][hf * 2 + e] + biasG[4][e]);
                    float cn = f * c_reg[im][hf][e] + i_ * z + Tg * s_reg[im][hf][e];
                    c_reg[im][hf][e] = cn;
                    h2[e] = o * tanhf(cn);
                }
                uint32_t hp = packbf(h2[0], h2[1]);
                *reinterpret_cast<uint32_t*>(&g_AB[(size_t)b * 640 + hhp]) = hp;
                if (t >= Tt - MEMN)
                    *reinterpret_cast<uint32_t*>(
                        &g_histB[(size_t)(t - (Tt - MEMN)) * (Bb * Hh) + b * 512 + hhp]) = hp;
                if (t == Tt - 1) {
                    g_h[b * 512 + hhp]     = h2[0];
                    g_h[b * 512 + hhp + 1] = h2[1];
                    g_c[b * 512 + hhp]     = c_reg[im][hf][0];
                    g_c[b * 512 + hhp + 1] = c_reg[im][hf][1];
                }
            }
        // stage x_{t+1}: CTA covers d-slice [hi*4, hi*4+4) for its 128 rows
        if (t < Tt - 1) {
            for (int i = tid; i < 512; i += NTHR) {
                int r = i >> 2, j = i & 3;
                int b = m0 + r, d = hi * 4 + j;
                g_AB[(size_t)b * 640 + 512 + d] =
                    __float2bfloat16(X[((size_t)b * Tt + (t + 1)) * (Dd + 1) + d]);
            }
        }
        bar += NCTA; gridbar(bar);
    }
}

// ---------------- tail: hsW = hist @ Wah^T (bf16 mma, double-buffered) ----------------
__global__ void __launch_bounds__(256) k_hsw() {
    __shared__ bf16 as[2][128 * 40];
    __shared__ bf16 bs[2][128 * 40];
    const int tid = threadIdx.x, w = tid >> 5, lane = tid & 31;
    const int lq = lane >> 2, lr = lane & 3;
    const int row0 = blockIdx.y * 128, col0 = blockIdx.x * 128;
    const int wm = w >> 1, wn = w & 1;

    float acc[2][8][4];
#pragma unroll
    for (int i = 0; i < 2; i++)
#pragma unroll
        for (int j = 0; j < 8; j++)
#pragma unroll
            for (int r = 0; r < 4; r++) acc[i][j][r] = 0.f;

    {
        int r = tid >> 1, part = (tid & 1) * 16;
        const bf16* sa = g_histB + (size_t)(row0 + r) * 512 + part;
        const bf16* sb = g_WahB + (size_t)(col0 + r) * 512 + part;
        cp16(&as[0][r * 40 + part], sa); cp16(&as[0][r * 40 + part + 8], sa + 8);
        cp16(&bs[0][r * 40 + part], sb); cp16(&bs[0][r * 40 + part + 8], sb + 8);
        cp_commit();
    }
    for (int ch = 0; ch < 16; ch++) {
        if (ch < 15) {
            int r = tid >> 1, part = (tid & 1) * 16;
            const bf16* sa = g_histB + (size_t)(row0 + r) * 512 + (ch + 1) * 32 + part;
            const bf16* sb = g_WahB + (size_t)(col0 + r) * 512 + (ch + 1) * 32 + part;
            int buf = (ch + 1) & 1;
            cp16(&as[buf][r * 40 + part], sa); cp16(&as[buf][r * 40 + part + 8], sa + 8);
            cp16(&bs[buf][r * 40 + part], sb); cp16(&bs[buf][r * 40 + part + 8], sb + 8);
            cp_commit(); cp_wait<1>();
        } else cp_wait<0>();
        __syncthreads();
        const bf16* ab = as[ch & 1];
        const bf16* bb2 = bs[ch & 1];
#pragma unroll
        for (int hf2 = 0; hf2 < 2; hf2++) {
            const int kk = hf2 * 16;
            uint32_t ar[2][4];
#pragma unroll
            for (int im = 0; im < 2; im++) {
                const bf16* ap = ab + (wm * 32 + im * 16 + lq) * 40 + kk + lr * 2;
                ar[im][0] = ld2bf(ap); ar[im][1] = ld2bf(ap + 8 * 40);
                ar[im][2] = ld2bf(ap + 8); ar[im][3] = ld2bf(ap + 8 * 40 + 8);
            }
#pragma unroll
            for (int jn = 0; jn < 8; jn++) {
                const bf16* bp = bb2 + (wn * 64 + jn * 8 + lq) * 40 + kk + lr * 2;
                uint32_t b0 = ld2bf(bp), b1 = ld2bf(bp + 8);
                mma16816(acc[0][jn], ar[0][0], ar[0][1], ar[0][2], ar[0][3], b0, b1);
                mma16816(acc[1][jn], ar[1][0], ar[1][1], ar[1][2], ar[1][3], b0, b1);
            }
        }
        __syncthreads();
    }
#pragma unroll
    for (int im = 0; im < 2; im++)
#pragma unroll
        for (int jn = 0; jn < 8; jn++)
#pragma unroll
            for (int hf = 0; hf < 2; hf++)
#pragma unroll
                for (int e = 0; e < 2; e++) {
                    int row = row0 + wm * 32 + im * 16 + lq + hf * 8;
                    int col = col0 + wn * 64 + jn * 8 + lr * 2 + e;
                    g_hsW[(size_t)row * 512 + col] = acc[im][jn][hf * 2 + e];
                }
}

__global__ void k_prepWah(const float* __restrict__ Wah) {
    int idx = blockIdx.x * 256 + threadIdx.x;
    if (idx < Hh * Hh) {
        int k = idx >> 9, n = idx & 511;
        g_WahB[n * 512 + k] = __float2bfloat16(Wah[k * 512 + n]);
    }
}

// ---------------- tf32 wmma plain GEMM (small tail GEMMs) ----------------
constexpr int PLDA = 68, PLDB = 132;
constexpr int SMEM_BYTES = (128 * PLDA + 64 * PLDB) * 4;

using FragA = wmma::fragment<wmma::matrix_a, 16, 16, 8, wmma::precision::tf32, wmma::row_major>;
using FragB = wmma::fragment<wmma::matrix_b, 16, 16, 8, wmma::precision::tf32, wmma::row_major>;
using FragC = wmma::fragment<wmma::accumulator, 16, 16, 8, float>;

__global__ void k_gemm_plain(const float* __restrict__ A, int lda,
                             const float* __restrict__ Bp, int ldb,
                             float* __restrict__ C, int ldc, int K, int beta) {
    extern __shared__ float smf[];
    float* As = smf;
    float* Bs = smf + 128 * PLDA;
    float* Cs = smf;
    const int tid = threadIdx.x, wid = tid >> 5, wm = wid >> 1, wn = wid & 1;
    const int row0 = blockIdx.y * 128, col0 = blockIdx.x * 128;

    FragC acc[2][4];
#pragma unroll
    for (int i = 0; i < 2; i++)
#pragma unroll
        for (int j = 0; j < 4; j++) wmma::fill_fragment(acc[i][j], 0.f);

    for (int kc = 0; kc < K; kc += 64) {
        for (int e = tid; e < 8192; e += 256) {
            int r = e >> 6, k = e & 63, kg = kc + k;
            float v = (kg < K) ? A[(size_t)(row0 + r) * lda + kg] : 0.f;
            As[r * PLDA + k] = wmma::__float_to_tf32(v);
        }
        for (int e = tid; e < 8192; e += 256) {
            int k = e >> 7, cc = e & 127, kg = kc + k;
            float v = (kg < K) ? Bp[(size_t)kg * ldb + col0 + cc] : 0.f;
            Bs[k * PLDB + cc] = wmma::__float_to_tf32(v);
        }
        __syncthreads();
#pragma unroll
        for (int kk = 0; kk < 64; kk += 8) {
            FragA a0, a1;
            wmma::load_matrix_sync(a0, As + (wm * 32) * PLDA + kk, PLDA);
            wmma::load_matrix_sync(a1, As + (wm * 32 + 16) * PLDA + kk, PLDA);
#pragma unroll
            for (int j = 0; j < 4; j++) {
                FragB bf;
                wmma::load_matrix_sync(bf, Bs + kk * PLDB + wn * 64 + j * 16, PLDB);
                wmma::mma_sync(acc[0][j], a0, bf, acc[0][j]);
                wmma::mma_sync(acc[1][j], a1, bf, acc[1][j]);
            }
        }
        __syncthreads();
    }
#pragma unroll
    for (int i = 0; i < 2; i++)
#pragma unroll
        for (int j = 0; j < 4; j++)
            wmma::store_matrix_sync(Cs + (wm * 32 + i * 16) * 128 + wn * 64 + j * 16,
                                    acc[i][j], 128, wmma::mem_row_major);
    __syncthreads();
    for (int e = tid; e < 16384; e += 256) {
        int r = e >> 7, cc = e & 127;
        size_t idx = (size_t)(row0 + r) * ldc + col0 + cc;
        C[idx] = Cs[e] + (beta ? C[idx] : 0.f);
    }
}

// ---------------- tail elementwise ----------------
__global__ void k_prep(const float* __restrict__ X) {
    int idx = blockIdx.x * 256 + threadIdx.x;
    if (idx < Bb * 2 * Hh) {
        int b = idx >> 10, k = idx & 1023;
        g_qbuf[idx] = (k < Hh) ? g_h[b * Hh + k] : g_c[b * Hh + (k - Hh)];
    }
    if (idx < Bb * Dd) {
        int b = idx >> 7, d = idx & 127;
        g_xlast[idx] = X[((size_t)b * Tt + (Tt - 1)) * (Dd + 1) + d];
    }
}

__global__ void k_scores(const float* __restrict__ baq, const float* __restrict__ bah,
                         const float* __restrict__ vt) {
    int wid = threadIdx.x >> 5, lane = threadIdx.x & 31;
    int r = blockIdx.x * 8 + wid;
    int b = r & 511;
    float acc = 0.f;
    for (int hh = lane; hh < Hh; hh += 32) {
        float x = g_hsW[(size_t)r * Hh + hh] + g_qW[b * Hh + hh] + baq[hh] + bah[hh];
        acc += tanhf(x) * vt[hh];
    }
#pragma unroll
    for (int o = 16; o; o >>= 1) acc += __shfl_down_sync(0xffffffffu, acc, o);
    if (lane == 0) g_scores[b * MEMN + (r >> 9)] = acc;
}

__global__ void k_softmax_e() {
    int b = blockIdx.x, tid = threadIdx.x;
    __shared__ float al[MEMN];
    __shared__ float ssum;
    if (tid < MEMN) al[tid] = expf(g_scores[b * MEMN + tid]);
    __syncthreads();
    if (tid == 0) {
        float s = 0.f;
        for (int m = 0; m < MEMN; m++) s += al[m];
        ssum = s;
    }
    __syncthreads();
    float inv = 1.f / ssum;
    for (int hh = tid; hh < Hh; hh += 256) {
        float acc = 0.f;
        for (int m = 0; m < MEMN; m++)
            acc += al[m] * __bfloat162float(g_histB[(size_t)m * (Bb * Hh) + b * Hh + hh]);
        g_e[b * Hh + hh] = acc * inv;
    }
}

__global__ void k_final(const float* __restrict__ b_Wh, const float* __restrict__ b_We,
                        const float* __restrict__ b_Wg, const float* __restrict__ bh_p,
                        const float* __restrict__ Wc, const float* __restrict__ bc,
                        float* __restrict__ out) {
    int b = blockIdx.x, tid = threadIdx.x;
    __shared__ float red[256];
    float acc = 0.f;
    for (int hh = tid; hh < Hh; hh += 256) {
        float hf = tanhf(g_hfin[b * Hh + hh] + b_Wh[hh] + b_We[hh] + b_Wg[hh] + bh_p[hh]);
        acc += hf * Wc[hh];
    }
    red[tid] = acc;
    __syncthreads();
    for (int s = 128; s; s >>= 1) {
        if (tid < s) red[tid] += red[tid + s];
        __syncthreads();
    }
    if (tid == 0) out[b] = 1.f / (1.f + expf(-(red[0] + bc[0])));
}

// ---------------- launch ----------------
extern "C" void kernel_launch(void* const* d_in, const int* in_sizes, int n_in,
                              void* d_out, int out_size) {
    const float* X      = (const float*)d_in[0];
    const float* Wh     = (const float*)d_in[1];
    const float* bh_lin = (const float*)d_in[2];
    const float* Wx     = (const float*)d_in[3];
    const float* bx_lin = (const float*)d_in[4];
    const float* Wst    = (const float*)d_in[5];
    const float* bst    = (const float*)d_in[6];
    const float* Ws     = (const float*)d_in[7];
    const float* bs_lin = (const float*)d_in[8];
    const float* bg     = (const float*)d_in[9];
    const float* Waq    = (const float*)d_in[10];
    const float* baq    = (const float*)d_in[11];
    const float* Wah    = (const float*)d_in[12];
    const float* bah    = (const float*)d_in[13];
    const float* vt     = (const float*)d_in[14];
    const float* W_h    = (const float*)d_in[15];
    const float* b_Wh   = (const float*)d_in[16];
    const float* We     = (const float*)d_in[17];
    const float* b_We   = (const float*)d_in[18];
    const float* Wg     = (const float*)d_in[19];
    const float* b_Wg   = (const float*)d_in[20];
    const float* bh_p   = (const float*)d_in[21];
    const float* Wc     = (const float*)d_in[22];
    const float* bc     = (const float*)d_in[23];
    float* out = (float*)d_out;

    cudaFuncSetAttribute(k_recur, cudaFuncAttributeMaxDynamicSharedMemorySize, SM_RECUR);
    cudaFuncSetAttribute(k_gemm_plain, cudaFuncAttributeMaxDynamicSharedMemorySize, SMEM_BYTES);

    float *p_qbuf, *p_qW, *p_h, *p_e, *p_xlast, *p_hfin;
    cudaGetSymbolAddress((void**)&p_qbuf,  g_qbuf);
    cudaGetSymbolAddress((void**)&p_qW,    g_qW);
    cudaGetSymbolAddress((void**)&p_h,     g_h);
    cudaGetSymbolAddress((void**)&p_e,     g_e);
    cudaGetSymbolAddress((void**)&p_xlast, g_xlast);
    cudaGetSymbolAddress((void**)&p_hfin,  g_hfin);

    k_init<<<(Bb * 640 + 255) / 256, 256>>>(X);
    k_recur<<<NCTA, NTHR, SM_RECUR>>>(X, Wh, Wx, Wst, Ws,
                                      bh_lin, bx_lin, bg, bst, bs_lin);

    k_prepWah<<<(Hh * Hh + 255) / 256, 256>>>(Wah);
    k_prep<<<(Bb * 2 * Hh + 255) / 256, 256>>>(X);
    k_gemm_plain<<<dim3(4, 4), 256, SMEM_BYTES>>>(p_qbuf, 2 * Hh, Waq, Hh, p_qW, Hh, 2 * Hh, 0);
    k_hsw<<<dim3(4, 256), 256>>>();
    k_scores<<<(MEMN * Bb) / 8, 256>>>(baq, bah, vt);
    k_softmax_e<<<Bb, 256>>>();
    k_gemm_plain<<<dim3(4, 4), 256, SMEM_BYTES>>>(p_h,     Hh, W_h, Hh, p_hfin, Hh, Hh, 0);
    k_gemm_plain<<<dim3(4, 4), 256, SMEM_BYTES>>>(p_e,     Hh, We,  Hh, p_hfin, Hh, Hh, 1);
    k_gemm_plain<<<dim3(4, 4), 256, SMEM_BYTES>>>(p_xlast, Dd, Wg,  Hh, p_hfin, Hh, Dd, 1);
    k_final<<<Bb, 256>>>(b_Wh, b_We, b_Wg, bh_p, Wc, bc, out);
}

// round 7
// speedup vs baseline: 2.9271x; 1.1888x over previous
#include <cuda_runtime.h>
#include <cuda_fp16.h>
#include <math.h>
#include <stdint.h>

constexpr int Bb = 512, Tt = 128, Dd = 128, Hh = 512, MEMN = 64;
constexpr int NCTA = 128, NTHR = 256;
constexpr int LD1 = 648, LD2 = 520;          // weight smem row strides (elems, 16B-aligned)
constexpr int SO_W1 = 0;
constexpr int SO_W2 = 96 * LD1 * 2;          // 124416
constexpr int SO_STG = SO_W2 + 80 * LD2 * 2; // 207616
constexpr int STG_BYTES = 128 * 64;          // 8192 per stage (128 rows x 64B, swizzled)
constexpr int SM_RECUR = SO_STG + 3 * STG_BYTES;  // 232192

// ---------------- device scratch ----------------
__device__ __half g_hB[Bb * Hh];                      // h, [b][512]
__device__ __half g_sB[Bb * Hh];                      // s_t, [b][512]
__device__ __half g_Xh[(size_t)Tt * Bb * Dd];         // x, [t][b][128]
__device__ float  g_dtT[Tt * Bb];                     // dt, [t][b]
__device__ __half g_histB[(size_t)MEMN * Bb * Hh];    // [m][b][h]
__device__ __half g_qh[Bb * 2 * Hh];                  // [b][ h | c ]
__device__ unsigned g_cnt;
// tail scratch
__device__ __half g_WahT[Hh * Hh];
__device__ __half g_WaqT[Hh * 2 * Hh];
__device__ __half g_WhT[Hh * Hh];
__device__ __half g_WeT[Hh * Hh];
__device__ __half g_WgT[Hh * Dd];
__device__ float g_qW[Bb * Hh];
__device__ float g_hsW[(size_t)MEMN * Bb * Hh];
__device__ float g_scores[Bb * MEMN];
__device__ __half g_eH[Bb * Hh];
__device__ float g_hfin[Bb * Hh];

// ---------------- helpers ----------------
__device__ __forceinline__ float sigmoidf_(float x) { return 1.f / (1.f + expf(-x)); }

__device__ __forceinline__ uint32_t packh2(float lo, float hi) {
    uint32_t r;
    asm("cvt.rn.f16x2.f32 %0, %1, %2;" : "=r"(r) : "f"(hi), "f"(lo));
    return r;
}
__device__ __forceinline__ uint32_t smem_u32(const void* p) {
    uint32_t a;
    asm("{ .reg .u64 t; cvta.to.shared.u64 t, %1; cvt.u32.u64 %0, t; }" : "=r"(a) : "l"(p));
    return a;
}
__device__ __forceinline__ void cp16b(uint32_t dst, const __half* src) {
    asm volatile("cp.async.cg.shared.global [%0], [%1], 16;" :: "r"(dst), "l"(src));
}
__device__ __forceinline__ void cp16s(__half* dst_smem, const __half* src) {
    uint32_t d = (uint32_t)__cvta_generic_to_shared(dst_smem);
    asm volatile("cp.async.cg.shared.global [%0], [%1], 16;" :: "r"(d), "l"(src));
}
__device__ __forceinline__ void cp_commit() { asm volatile("cp.async.commit_group;"); }
template <int N>
__device__ __forceinline__ void cp_wait() { asm volatile("cp.async.wait_group %0;" :: "n"(N)); }

__device__ __forceinline__ void ldsm4(uint32_t* r, uint32_t a) {
    asm volatile("ldmatrix.sync.aligned.m8n8.x4.shared.b16 {%0,%1,%2,%3}, [%4];"
                 : "=r"(r[0]), "=r"(r[1]), "=r"(r[2]), "=r"(r[3]) : "r"(a));
}
__device__ __forceinline__ void ldsm2(uint32_t* r, uint32_t a) {
    asm volatile("ldmatrix.sync.aligned.m8n8.x2.shared.b16 {%0,%1}, [%2];"
                 : "=r"(r[0]), "=r"(r[1]) : "r"(a));
}
__device__ __forceinline__ uint32_t ldu32(const __half* p) {
    return *reinterpret_cast<const uint32_t*>(p);
}
// f16 accumulate (2 regs)
__device__ __forceinline__ void mma16816h(uint32_t* c, uint32_t a0, uint32_t a1,
                                          uint32_t a2, uint32_t a3, uint32_t b0, uint32_t b1) {
    asm volatile(
        "mma.sync.aligned.m16n8k16.row.col.f16.f16.f16.f16 "
        "{%0,%1}, {%2,%3,%4,%5}, {%6,%7}, {%0,%1};"
        : "+r"(c[0]), "+r"(c[1])
        : "r"(a0), "r"(a1), "r"(a2), "r"(a3), "r"(b0), "r"(b1));
}
// f32 accumulate (tail)
__device__ __forceinline__ void mma16816f(float* c, uint32_t a0, uint32_t a1, uint32_t a2,
                                          uint32_t a3, uint32_t b0, uint32_t b1) {
    asm volatile(
        "mma.sync.aligned.m16n8k16.row.col.f32.f16.f16.f32 "
        "{%0,%1,%2,%3}, {%4,%5,%6,%7}, {%8,%9}, {%0,%1,%2,%3};"
        : "+f"(c[0]), "+f"(c[1]), "+f"(c[2]), "+f"(c[3])
        : "r"(a0), "r"(a1), "r"(a2), "r"(a3), "r"(b0), "r"(b1));
}
__device__ __forceinline__ void gridbar(unsigned target) {
    __syncthreads();
    if (threadIdx.x == 0) {
        __threadfence();
        atomicAdd(&g_cnt, 1u);
        unsigned v;
        do {
            asm volatile("ld.acquire.gpu.u32 %0, [%1];" : "=r"(v) : "l"(&g_cnt) : "memory");
        } while (v < target);
    }
    __syncthreads();
}

// ---------------- init: transpose/pack X, zero h ----------------
__global__ void k_init(const float* __restrict__ X) {
    int idx = blockIdx.x * 256 + threadIdx.x;
    if (idx == 0) g_cnt = 0;
    if (idx < Bb * Hh / 2) reinterpret_cast<uint32_t*>(g_hB)[idx] = 0u;
    if (idx < Tt * Bb) {
        int t = idx >> 9, b = idx & 511;
        g_dtT[idx] = X[((size_t)b * Tt + t) * (Dd + 1) + Dd];
    }
    if (idx < Tt * Bb * (Dd / 2)) {
        int dp = idx & 63, rem = idx >> 6;
        int b = rem & 511, t = rem >> 9;
        const float* xp = X + ((size_t)b * Tt + t) * (Dd + 1) + 2 * dp;
        reinterpret_cast<uint32_t*>(g_Xh)[idx] = packh2(xp[0], xp[1]);
    }
}

// ---------------- weight transpose/pack (tail) ----------------
__global__ void k_packT(const float* __restrict__ W, __half* __restrict__ out, int K, int N) {
    int idx = blockIdx.x * 256 + threadIdx.x;
    if (idx >= K * N) return;
    int n = idx / K, k = idx - n * K;
    out[idx] = __float2half(W[(size_t)k * N + n]);
}

// ---------------- persistent recurrent kernel ----------------
__global__ void __launch_bounds__(NTHR, 1)
k_recur(const float* __restrict__ Wh, const float* __restrict__ Wx,
        const float* __restrict__ Wst, const float* __restrict__ Ws,
        const float* __restrict__ bh_lin, const float* __restrict__ bx_lin,
        const float* __restrict__ bg, const float* __restrict__ bst,
        const float* __restrict__ bs_lin) {
    extern __shared__ __align__(16) __half sm[];
    const uint32_t sbase = smem_u32(sm);
    const uint32_t w1u = sbase + SO_W1, w2u = sbase + SO_W2, stgu = sbase + SO_STG;
    __half* w1s = sm;
    __half* w2s = sm + 96 * LD1;

    const int tid = threadIdx.x, cta = blockIdx.x;
    const int w = tid >> 5, lane = tid & 31;
    const int lq = lane >> 2, lr = lane & 3;
    const int wm = w >> 1, wn = w & 1;          // 4x2 warps: 32 rows x 48/40 cols
    const int mi = cta & 3, hi = cta >> 2;
    const int m0 = mi * 128, hh0 = hi * 16;

    // ---- weight slices into SMEM (once) ----
    for (int idx = tid; idx < 96 * 640; idx += NTHR) {
        int n = idx / 640, k = idx - n * 640;
        int wn_ = n / 48, rem = n - wn_ * 48, jn = rem >> 3, c = rem & 7;
        int g = (jn < 5) ? jn + 1 : 0;
        int hh = hh0 + wn_ * 8 + c;
        float v = (k < 512) ? Wh[((size_t)(g * 512 + k)) * 512 + hh]
                            : Wx[((size_t)(g * 128 + (k - 512))) * 512 + hh];
        w1s[n * LD1 + k] = __float2half(v);
    }
    for (int idx = tid; idx < 80 * 512; idx += NTHR) {
        int n = idx >> 9, k = idx & 511;
        int wn_ = n / 40, rem = n - wn_ * 40, jn = rem >> 3, c = rem & 7;
        int hh = hh0 + wn_ * 8 + c;
        w2s[n * LD2 + k] = __float2half(Ws[((size_t)(jn * 512 + k)) * 512 + hh]);
    }
    __syncthreads();

    // ---- per-thread constants ----
    const int hhp = hh0 + wn * 8 + lr * 2;
    float biasG[5][2], bias0[2], wstv[2];
#pragma unroll
    for (int e = 0; e < 2; e++) {
        int hh = hhp + e;
        bias0[e] = bh_lin[hh] + bx_lin[hh] + bg[hh] + bst[hh];
        wstv[e] = Wst[hh];
#pragma unroll
        for (int q = 0; q < 5; q++) {
            int gc = (q + 1) * 512 + hh;
            biasG[q][e] = bh_lin[gc] + bx_lin[gc] + bg[gc] + bs_lin[q * 512 + hh];
        }
    }

    // ---- precomputed ldmatrix address components ----
    const int hi4 = (lane >> 4) & 1;
    uint32_t rowA[2], swzA[2];
#pragma unroll
    for (int im = 0; im < 2; im++) {
        int R = wm * 32 + im * 16 + (lane & 15);
        rowA[im] = (uint32_t)R * 64u;
        swzA[im] = (uint32_t)((R >> 1) & 3);
    }
    uint32_t boff1[3];
#pragma unroll
    for (int p = 0; p < 3; p++) {
        int n = wn * 48 + p * 16 + (lane & 7) + ((lane & 16) >> 1);
        boff1[p] = (uint32_t)n * (LD1 * 2) + ((lane & 8) << 1);
    }
    uint32_t boff2[2], boff2x;
#pragma unroll
    for (int p = 0; p < 2; p++) {
        int n = wn * 40 + p * 16 + (lane & 7) + ((lane & 16) >> 1);
        boff2[p] = (uint32_t)n * (LD2 * 2) + ((lane & 8) << 1);
    }
    {
        int n = wn * 40 + 32 + (lane & 7);
        boff2x = (uint32_t)n * (LD2 * 2) + ((lane & 8) << 1);
    }
    // staging writer: row r = tid>>1, segs s0, s0+1
    const int str = tid >> 1, ss0 = (tid & 1) * 2;
    const uint32_t swr = (uint32_t)((str >> 1) & 3);
    const uint32_t wdst0 = (uint32_t)str * 64u + (((uint32_t)ss0 ^ swr) & 3u) * 16u;
    const uint32_t wdst1 = (uint32_t)str * 64u + (((uint32_t)(ss0 + 1) ^ swr) & 3u) * 16u;

    float c_reg[2][2][2], s_reg[2][2][2];
#pragma unroll
    for (int i = 0; i < 2; i++)
#pragma unroll
        for (int j = 0; j < 2; j++) { c_reg[i][j][0] = 0.f; c_reg[i][j][1] = 0.f; }

    unsigned bar = 0;

    for (int t = 0; t < Tt; t++) {
        uint32_t acc[2][6][2];
#pragma unroll
        for (int i = 0; i < 2; i++)
#pragma unroll
            for (int j = 0; j < 6; j++) { acc[i][j][0] = 0u; acc[i][j][1] = 0u; }

        // ===== phase 1: [h | x_t] @ W1, K=640, 20 chunks (16 h + 4 x), 3-stage pipe =====
        {
            const __half* hrow = g_hB + (size_t)(m0 + str) * 512 + ss0 * 8;
            const __half* xrow = g_Xh + ((size_t)t * 512 + m0 + str) * 128 + ss0 * 8;
            // prologue: stage chunks 0,1
            cp16b(stgu + 0 * STG_BYTES + wdst0, hrow);
            cp16b(stgu + 0 * STG_BYTES + wdst1, hrow + 8);
            cp_commit();
            cp16b(stgu + 1 * STG_BYTES + wdst0, hrow + 32);
            cp16b(stgu + 1 * STG_BYTES + wdst1, hrow + 40);
            cp_commit();
            int st = 0;
            for (int ch = 0; ch < 20; ch++) {
                if (ch < 19) cp_wait<1>(); else cp_wait<0>();
                __syncthreads();
                if (ch + 2 < 20) {
                    int c2 = ch + 2;
                    int s2 = st + 2; if (s2 >= 3) s2 -= 3;
                    const __half* src = (c2 < 16) ? hrow + c2 * 32 : xrow + (c2 - 16) * 32;
                    cp16b(stgu + s2 * STG_BYTES + wdst0, src);
                    cp16b(stgu + s2 * STG_BYTES + wdst1, src + 8);
                    cp_commit();
                }
                const uint32_t abuf = stgu + st * STG_BYTES;
                const uint32_t kb = (uint32_t)ch * 64u;
#pragma unroll
                for (int half = 0; half < 2; half++) {
                    uint32_t A0[4], A1[4], Bv[12];
                    uint32_t sseg = (uint32_t)(half * 2 + hi4);
                    ldsm4(A0, abuf + rowA[0] + ((sseg ^ swzA[0]) & 3u) * 16u);
                    ldsm4(A1, abuf + rowA[1] + ((sseg ^ swzA[1]) & 3u) * 16u);
                    uint32_t kw = kb + (uint32_t)half * 32u;
                    ldsm4(Bv + 0, w1u + boff1[0] + kw);
                    ldsm4(Bv + 4, w1u + boff1[1] + kw);
                    ldsm4(Bv + 8, w1u + boff1[2] + kw);
#pragma unroll
                    for (int jn = 0; jn < 6; jn++) {
                        mma16816h(acc[0][jn], A0[0], A0[1], A0[2], A0[3], Bv[2 * jn], Bv[2 * jn + 1]);
                        mma16816h(acc[1][jn], A1[0], A1[1], A1[2], A1[3], Bv[2 * jn], Bv[2 * jn + 1]);
                    }
                }
                if (++st == 3) st = 0;
            }
        }
        // mid epilogue: s = tanh(pre0 + dt*Wst + bias)
#pragma unroll
        for (int im = 0; im < 2; im++)
#pragma unroll
            for (int hf = 0; hf < 2; hf++) {
                int b = m0 + wm * 32 + im * 16 + lq + hf * 8;
                float dt = g_dtT[t * 512 + b];
                float2 pv = __half22float2(*reinterpret_cast<__half2*>(&acc[im][5][hf]));
                float s0 = tanhf(pv.x + bias0[0] + dt * wstv[0]);
                float s1 = tanhf(pv.y + bias0[1] + dt * wstv[1]);
                s_reg[im][hf][0] = s0; s_reg[im][hf][1] = s1;
                *reinterpret_cast<uint32_t*>(&g_sB[(size_t)b * 512 + hhp]) = packh2(s0, s1);
            }
        bar += NCTA; gridbar(bar);

        // ===== phase 2: s @ Ws accumulates onto same acc, K=512, 16 chunks =====
        {
            const __half* srow = g_sB + (size_t)(m0 + str) * 512 + ss0 * 8;
            cp16b(stgu + 0 * STG_BYTES + wdst0, srow);
            cp16b(stgu + 0 * STG_BYTES + wdst1, srow + 8);
            cp_commit();
            cp16b(stgu + 1 * STG_BYTES + wdst0, srow + 32);
            cp16b(stgu + 1 * STG_BYTES + wdst1, srow + 40);
            cp_commit();
            int st = 0;
            for (int ch = 0; ch < 16; ch++) {
                if (ch < 15) cp_wait<1>(); else cp_wait<0>();
                __syncthreads();
                if (ch + 2 < 16) {
                    int s2 = st + 2; if (s2 >= 3) s2 -= 3;
                    const __half* src = srow + (ch + 2) * 32;
                    cp16b(stgu + s2 * STG_BYTES + wdst0, src);
                    cp16b(stgu + s2 * STG_BYTES + wdst1, src + 8);
                    cp_commit();
                }
                const uint32_t abuf = stgu + st * STG_BYTES;
                const uint32_t kb = (uint32_t)ch * 64u;
#pragma unroll
                for (int half = 0; half < 2; half++) {
                    uint32_t A0[4], A1[4], Bv[10];
                    uint32_t sseg = (uint32_t)(half * 2 + hi4);
                    ldsm4(A0, abuf + rowA[0] + ((sseg ^ swzA[0]) & 3u) * 16u);
                    ldsm4(A1, abuf + rowA[1] + ((sseg ^ swzA[1]) & 3u) * 16u);
                    uint32_t kw = kb + (uint32_t)half * 32u;
                    ldsm4(Bv + 0, w2u + boff2[0] + kw);
                    ldsm4(Bv + 4, w2u + boff2[1] + kw);
                    ldsm2(Bv + 8, w2u + boff2x + kw);
#pragma unroll
                    for (int jn = 0; jn < 5; jn++) {
                        mma16816h(acc[0][jn], A0[0], A0[1], A0[2], A0[3], Bv[2 * jn], Bv[2 * jn + 1]);
                        mma16816h(acc[1][jn], A1[0], A1[1], A1[2], A1[3], Bv[2 * jn], Bv[2 * jn + 1]);
                    }
                }
                if (++st == 3) st = 0;
            }
        }
        // end epilogue: fused LSTM state update (c in registers)
#pragma unroll
        for (int im = 0; im < 2; im++)
#pragma unroll
            for (int hf = 0; hf < 2; hf++) {
                int b = m0 + wm * 32 + im * 16 + lq + hf * 8;
                float2 gv[5];
#pragma unroll
                for (int q = 0; q < 5; q++)
                    gv[q] = __half22float2(*reinterpret_cast<__half2*>(&acc[im][q][hf]));
                float h2[2];
#pragma unroll
                for (int e = 0; e < 2; e++) {
                    float p0 = e ? gv[0].y : gv[0].x;
                    float p1 = e ? gv[1].y : gv[1].x;
                    float p2 = e ? gv[2].y : gv[2].x;
                    float p3 = e ? gv[3].y : gv[3].x;
                    float p4 = e ? gv[4].y : gv[4].x;
                    float f  = sigmoidf_(p0 + biasG[0][e]);
                    float i_ = sigmoidf_(p1 + biasG[1][e]);
                    float Tg = sigmoidf_(p2 + biasG[2][e]);
                    float z  = tanhf(p3 + biasG[3][e]);
                    float o  = sigmoidf_(p4 + biasG[4][e]);
                    float cn = f * c_reg[im][hf][e] + i_ * z + Tg * s_reg[im][hf][e];
                    c_reg[im][hf][e] = cn;
                    h2[e] = o * tanhf(cn);
                }
                uint32_t hp = packh2(h2[0], h2[1]);
                *reinterpret_cast<uint32_t*>(&g_hB[(size_t)b * 512 + hhp]) = hp;
                if (t >= Tt - MEMN)
                    *reinterpret_cast<uint32_t*>(
                        &g_histB[(size_t)(t - (Tt - MEMN)) * (Bb * Hh) + (size_t)b * 512 + hhp]) = hp;
                if (t == Tt - 1) {
                    *reinterpret_cast<uint32_t*>(&g_qh[(size_t)b * 1024 + hhp]) = hp;
                    *reinterpret_cast<uint32_t*>(&g_qh[(size_t)b * 1024 + 512 + hhp]) =
                        packh2(c_reg[im][hf][0], c_reg[im][hf][1]);
                }
            }
        bar += NCTA; gridbar(bar);
    }
}

// ---------------- generic f16 GEMM (f32 acc): C[m][n] (+)= A[m][:] . Bt[n][:] ----------------
__global__ void __launch_bounds__(256) k_gemm16(const __half* __restrict__ A,
                                                const __half* __restrict__ Bt,
                                                float* __restrict__ C,
                                                int K, int ldc, int beta) {
    __shared__ __half as[2][128 * 40];
    __shared__ __half bs[2][128 * 40];
    const int tid = threadIdx.x, w = tid >> 5, lane = tid & 31;
    const int lq = lane >> 2, lr = lane & 3;
    const int row0 = blockIdx.y * 128, col0 = blockIdx.x * 128;
    const int wm = w >> 1, wn = w & 1;
    const int nch = K >> 5;

    float acc[2][8][4];
#pragma unroll
    for (int i = 0; i < 2; i++)
#pragma unroll
        for (int j = 0; j < 8; j++)
#pragma unroll
            for (int r = 0; r < 4; r++) acc[i][j][r] = 0.f;

    const int r = tid >> 1, part = (tid & 1) * 16;
    const __half* sa0 = A + (size_t)(row0 + r) * K + part;
    const __half* sb0 = Bt + (size_t)(col0 + r) * K + part;
    {
        cp16s(&as[0][r * 40 + part], sa0); cp16s(&as[0][r * 40 + part + 8], sa0 + 8);
        cp16s(&bs[0][r * 40 + part], sb0); cp16s(&bs[0][r * 40 + part + 8], sb0 + 8);
        cp_commit();
    }
    for (int ch = 0; ch < nch; ch++) {
        if (ch < nch - 1) {
            int buf = (ch + 1) & 1;
            const __half* sa = sa0 + (ch + 1) * 32;
            const __half* sb = sb0 + (ch + 1) * 32;
            cp16s(&as[buf][r * 40 + part], sa); cp16s(&as[buf][r * 40 + part + 8], sa + 8);
            cp16s(&bs[buf][r * 40 + part], sb); cp16s(&bs[buf][r * 40 + part + 8], sb + 8);
            cp_commit(); cp_wait<1>();
        } else cp_wait<0>();
        __syncthreads();
        const __half* ab = as[ch & 1];
        const __half* bb2 = bs[ch & 1];
#pragma unroll
        for (int hf2 = 0; hf2 < 2; hf2++) {
            const int kk = hf2 * 16;
            uint32_t ar[2][4];
#pragma unroll
            for (int im = 0; im < 2; im++) {
                const __half* ap = ab + (wm * 32 + im * 16 + lq) * 40 + kk + lr * 2;
                ar[im][0] = ldu32(ap); ar[im][1] = ldu32(ap + 8 * 40);
                ar[im][2] = ldu32(ap + 8); ar[im][3] = ldu32(ap + 8 * 40 + 8);
            }
#pragma unroll
            for (int jn = 0; jn < 8; jn++) {
                const __half* bp = bb2 + (wn * 64 + jn * 8 + lq) * 40 + kk + lr * 2;
                uint32_t b0 = ldu32(bp), b1 = ldu32(bp + 8);
                mma16816f(acc[0][jn], ar[0][0], ar[0][1], ar[0][2], ar[0][3], b0, b1);
                mma16816f(acc[1][jn], ar[1][0], ar[1][1], ar[1][2], ar[1][3], b0, b1);
            }
        }
        __syncthreads();
    }
#pragma unroll
    for (int im = 0; im < 2; im++)
#pragma unroll
        for (int jn = 0; jn < 8; jn++)
#pragma unroll
            for (int hf = 0; hf < 2; hf++)
#pragma unroll
                for (int e = 0; e < 2; e++) {
                    int row = row0 + wm * 32 + im * 16 + lq + hf * 8;
                    int col = col0 + wn * 64 + jn * 8 + lr * 2 + e;
                    size_t idx = (size_t)row * ldc + col;
                    float v = acc[im][jn][hf * 2 + e];
                    C[idx] = beta ? (C[idx] + v) : v;
                }
}

// ---------------- tail elementwise ----------------
__global__ void k_scores(const float* __restrict__ baq, const float* __restrict__ bah,
                         const float* __restrict__ vt) {
    int wid = threadIdx.x >> 5, lane = threadIdx.x & 31;
    int r = blockIdx.x * 8 + wid;
    int b = r & 511;
    float acc = 0.f;
    for (int hh = lane; hh < Hh; hh += 32) {
        float x = g_hsW[(size_t)r * Hh + hh] + g_qW[b * Hh + hh] + baq[hh] + bah[hh];
        acc += tanhf(x) * vt[hh];
    }
#pragma unroll
    for (int o = 16; o; o >>= 1) acc += __shfl_down_sync(0xffffffffu, acc, o);
    if (lane == 0) g_scores[b * MEMN + (r >> 9)] = acc;
}

__global__ void k_softmax_e() {
    int b = blockIdx.x, tid = threadIdx.x;
    __shared__ float al[MEMN];
    __shared__ float ssum;
    if (tid < MEMN) al[tid] = expf(g_scores[b * MEMN + tid]);
    __syncthreads();
    if (tid == 0) {
        float s = 0.f;
        for (int m = 0; m < MEMN; m++) s += al[m];
        ssum = s;
    }
    __syncthreads();
    float inv = 1.f / ssum;
    for (int hh = tid; hh < Hh; hh += 256) {
        float acc = 0.f;
        for (int m = 0; m < MEMN; m++)
            acc += al[m] * __half2float(g_histB[(size_t)m * (Bb * Hh) + b * Hh + hh]);
        g_eH[b * Hh + hh] = __float2half(acc * inv);
    }
}

__global__ void k_final(const float* __restrict__ b_Wh, const float* __restrict__ b_We,
                        const float* __restrict__ b_Wg, const float* __restrict__ bh_p,
                        const float* __restrict__ Wc, const float* __restrict__ bc,
                        float* __restrict__ out) {
    int b = blockIdx.x, tid = threadIdx.x;
    __shared__ float red[256];
    float acc = 0.f;
    for (int hh = tid; hh < Hh; hh += 256) {
        float hf = tanhf(g_hfin[b * Hh + hh] + b_Wh[hh] + b_We[hh] + b_Wg[hh] + bh_p[hh]);
        acc += hf * Wc[hh];
    }
    red[tid] = acc;
    __syncthreads();
    for (int s = 128; s; s >>= 1) {
        if (tid < s) red[tid] += red[tid + s];
        __syncthreads();
    }
    if (tid == 0) out[b] = 1.f / (1.f + expf(-(red[0] + bc[0])));
}

// ---------------- launch ----------------
extern "C" void kernel_launch(void* const* d_in, const int* in_sizes, int n_in,
                              void* d_out, int out_size) {
    const float* X      = (const float*)d_in[0];
    const float* Wh     = (const float*)d_in[1];
    const float* bh_lin = (const float*)d_in[2];
    const float* Wx     = (const float*)d_in[3];
    const float* bx_lin = (const float*)d_in[4];
    const float* Wst    = (const float*)d_in[5];
    const float* bst    = (const float*)d_in[6];
    const float* Ws     = (const float*)d_in[7];
    const float* bs_lin = (const float*)d_in[8];
    const float* bg     = (const float*)d_in[9];
    const float* Waq    = (const float*)d_in[10];
    const float* baq    = (const float*)d_in[11];
    const float* Wah    = (const float*)d_in[12];
    const float* bah    = (const float*)d_in[13];
    const float* vt     = (const float*)d_in[14];
    const float* W_h    = (const float*)d_in[15];
    const float* b_Wh   = (const float*)d_in[16];
    const float* We     = (const float*)d_in[17];
    const float* b_We   = (const float*)d_in[18];
    const float* Wg     = (const float*)d_in[19];
    const float* b_Wg   = (const float*)d_in[20];
    const float* bh_p   = (const float*)d_in[21];
    const float* Wc     = (const float*)d_in[22];
    const float* bc     = (const float*)d_in[23];
    float* out = (float*)d_out;

    cudaFuncSetAttribute(k_recur, cudaFuncAttributeMaxDynamicSharedMemorySize, SM_RECUR);

    __half *p_Xh, *p_hist, *p_qh, *p_hB, *p_eH;
    __half *p_WahT, *p_WaqT, *p_WhT, *p_WeT, *p_WgT;
    float *p_qW, *p_hsW, *p_hfin;
    cudaGetSymbolAddress((void**)&p_Xh,   g_Xh);
    cudaGetSymbolAddress((void**)&p_hist, g_histB);
    cudaGetSymbolAddress((void**)&p_qh,   g_qh);
    cudaGetSymbolAddress((void**)&p_hB,   g_hB);
    cudaGetSymbolAddress((void**)&p_eH,   g_eH);
    cudaGetSymbolAddress((void**)&p_WahT, g_WahT);
    cudaGetSymbolAddress((void**)&p_WaqT, g_WaqT);
    cudaGetSymbolAddress((void**)&p_WhT,  g_WhT);
    cudaGetSymbolAddress((void**)&p_WeT,  g_WeT);
    cudaGetSymbolAddress((void**)&p_WgT,  g_WgT);
    cudaGetSymbolAddress((void**)&p_qW,   g_qW);
    cudaGetSymbolAddress((void**)&p_hsW,  g_hsW);
    cudaGetSymbolAddress((void**)&p_hfin, g_hfin);

    // init: X transpose/pack + zero h (covers largest domain: Tt*Bb*64 u32)
    k_init<<<(Tt * Bb * (Dd / 2) + 255) / 256, 256>>>(X);
    // weight transposes for tail (independent of recurrence)
    k_packT<<<(Hh * Hh + 255) / 256, 256>>>(Wah, p_WahT, Hh, Hh);
    k_packT<<<(2 * Hh * Hh + 255) / 256, 256>>>(Waq, p_WaqT, 2 * Hh, Hh);
    k_packT<<<(Hh * Hh + 255) / 256, 256>>>(W_h, p_WhT, Hh, Hh);
    k_packT<<<(Hh * Hh + 255) / 256, 256>>>(We, p_WeT, Hh, Hh);
    k_packT<<<(Dd * Hh + 255) / 256, 256>>>(Wg, p_WgT, Dd, Hh);

    k_recur<<<NCTA, NTHR, SM_RECUR>>>(Wh, Wx, Wst, Ws,
                                      bh_lin, bx_lin, bg, bst, bs_lin);

    // attention + readout
    k_gemm16<<<dim3(4, 4),   256>>>(p_qh,   p_WaqT, p_qW,   1024, 512, 0);
    k_gemm16<<<dim3(4, 256), 256>>>(p_hist, p_WahT, p_hsW,  512,  512, 0);
    k_scores<<<(MEMN * Bb) / 8, 256>>>(baq, bah, vt);
    k_softmax_e<<<Bb, 256>>>();
    k_gemm16<<<dim3(4, 4), 256>>>(p_hB, p_WhT, p_hfin, 512, 512, 0);
    k_gemm16<<<dim3(4, 4), 256>>>(p_eH, p_WeT, p_hfin, 512, 512, 1);
    k_gemm16<<<dim3(4, 4), 256>>>(p_Xh + (size_t)(Tt - 1) * Bb * Dd, p_WgT, p_hfin, 128, 512, 1);
    k_final<<<Bb, 256>>>(b_Wh, b_We, b_Wg, bh_p, Wc, bc, out);
}